// round 1
// baseline (speedup 1.0000x reference)
#include <cuda_runtime.h>
#include <math.h>

// Problem constants
#define MDIM 16384          // B*N = 2*8192 rows
#define EDIM 1024           // embed
#define HN   16             // heads
#define DH   64             // head dim
#define NCH  64             // chunks per sequence (8192/128)
#define BHN  32             // B*H

// ---------------- scratch (device globals; no allocation allowed) ------------
__device__ float gQ[MDIM * EDIM];
__device__ float gK[MDIM * EDIM];
__device__ float gV[MDIM * EDIM];
__device__ float gO[MDIM * EDIM];
__device__ float gGATE[MDIM * EDIM];
__device__ float gG1[MDIM * DH];
__device__ float gM[BHN * NCH * DH * DH];
__device__ float gKV[BHN * NCH * DH * DH];

__device__ __forceinline__ float head_slope(int h) {
    // slopes for H=16: 2^{-0.5*(h+1)}, scaled by (1 - 0/(12-1) + 1e-5)
    return exp2f(-0.5f * (float)(h + 1)) * 1.00001f;
}

template <int EPI>
__device__ __forceinline__ float epilogue(float v) {
    if (EPI == 1) return v / (1.f + expf(-v));      // silu
    if (EPI == 2) return 1.f / (1.f + expf(-v));    // sigmoid
    return v;
}

// ---------------- generic SGEMM: C = epi(A @ B), row-major ------------------
// 128x128 tile, K-tile 8, 256 threads, 8x8 per thread, double-buffered smem.
template <int EPI>
__global__ __launch_bounds__(256) void sgemm_k(
    const float* __restrict__ A, const float* __restrict__ B,
    float* __restrict__ C, int M, int N, int K)
{
    __shared__ float As[2][8][128];
    __shared__ float Bs[2][8][128];

    const int tid = threadIdx.x;
    const int tx = tid & 15, ty = tid >> 4;
    const int bm = blockIdx.y << 7, bn = blockIdx.x << 7;

    const int arow = tid >> 1, acol = (tid & 1) << 2;
    const int brow = tid >> 5, bcol = (tid & 31) << 2;
    const int gArow = bm + arow;
    const bool aok = gArow < M;
    const bool bok = (bn + bcol) < N;
    const float4 f4z = make_float4(0.f, 0.f, 0.f, 0.f);

    float4 av = aok ? *(const float4*)(A + (size_t)gArow * K + acol) : f4z;
    float4 bv = bok ? *(const float4*)(B + (size_t)brow * N + bn + bcol) : f4z;

    As[0][acol + 0][arow] = av.x; As[0][acol + 1][arow] = av.y;
    As[0][acol + 2][arow] = av.z; As[0][acol + 3][arow] = av.w;
    *(float4*)&Bs[0][brow][bcol] = bv;
    __syncthreads();

    float acc[8][8];
#pragma unroll
    for (int i = 0; i < 8; i++)
#pragma unroll
        for (int j = 0; j < 8; j++) acc[i][j] = 0.f;

    int buf = 0;
    for (int k0 = 0; k0 < K; k0 += 8) {
        const bool more = (k0 + 8) < K;
        if (more) {
            av = aok ? *(const float4*)(A + (size_t)gArow * K + k0 + 8 + acol) : f4z;
            bv = bok ? *(const float4*)(B + (size_t)(k0 + 8 + brow) * N + bn + bcol) : f4z;
        }
#pragma unroll
        for (int k = 0; k < 8; k++) {
            float4 a0 = *(float4*)&As[buf][k][ty << 2];
            float4 a1 = *(float4*)&As[buf][k][64 + (ty << 2)];
            float4 b0 = *(float4*)&Bs[buf][k][tx << 2];
            float4 b1 = *(float4*)&Bs[buf][k][64 + (tx << 2)];
            float ar[8] = {a0.x, a0.y, a0.z, a0.w, a1.x, a1.y, a1.z, a1.w};
            float br[8] = {b0.x, b0.y, b0.z, b0.w, b1.x, b1.y, b1.z, b1.w};
#pragma unroll
            for (int i = 0; i < 8; i++)
#pragma unroll
                for (int j = 0; j < 8; j++)
                    acc[i][j] = fmaf(ar[i], br[j], acc[i][j]);
        }
        if (more) {
            buf ^= 1;
            As[buf][acol + 0][arow] = av.x; As[buf][acol + 1][arow] = av.y;
            As[buf][acol + 2][arow] = av.z; As[buf][acol + 3][arow] = av.w;
            *(float4*)&Bs[buf][brow][bcol] = bv;
            __syncthreads();
        }
    }

#pragma unroll
    for (int ii = 0; ii < 8; ii++) {
        const int row = bm + ((ii < 4) ? ((ty << 2) + ii) : (64 + (ty << 2) + ii - 4));
        if (row >= M) continue;
#pragma unroll
        for (int half = 0; half < 2; half++) {
            const int col = bn + (half << 6) + (tx << 2);
            if (col < N) {
                float4 o;
                o.x = epilogue<EPI>(acc[ii][half * 4 + 0]);
                o.y = epilogue<EPI>(acc[ii][half * 4 + 1]);
                o.z = epilogue<EPI>(acc[ii][half * 4 + 2]);
                o.w = epilogue<EPI>(acc[ii][half * 4 + 3]);
                *(float4*)(C + (size_t)row * N + col) = o;
            }
        }
    }
}

// ------------- pass A: per-chunk M = K^T diag(lamk) V  [64x64] --------------
__global__ __launch_bounds__(256) void chunk_kv_k(
    const float* __restrict__ Kg, const float* __restrict__ Vg,
    float* __restrict__ Mo)
{
    __shared__ float Ks[64][68];
    __shared__ float Vs[64][68];
    __shared__ float dpw[132];

    const int c = blockIdx.x, bh = blockIdx.y;
    const int b = bh >> 4, h = bh & 15;
    const int tid = threadIdx.x;
    const float s = head_slope(h);
    if (tid < 129) dpw[tid] = expf(-s * (float)tid);
    __syncthreads();

    const int tx = tid & 15, ty = tid >> 4;
    float acc[4][4];
#pragma unroll
    for (int i = 0; i < 4; i++)
#pragma unroll
        for (int j = 0; j < 4; j++) acc[i][j] = 0.f;

    const size_t rowbase = (size_t)b * 8192 + (size_t)c * 128;
    const int colbase = h * 64;

    for (int half = 0; half < 2; ++half) {
        if (half) __syncthreads();
        const int r = tid >> 2;
        const int f0 = tid & 3;
        const int jg = (half << 6) + r;          // position in chunk
        const float lk = dpw[127 - jg];
        const size_t gr = (rowbase + jg) * 1024 + colbase;
#pragma unroll
        for (int it = 0; it < 4; ++it) {
            const int f = f0 + (it << 2);
            float4 k4 = *(const float4*)(Kg + gr + (f << 2));
            float4 v4 = *(const float4*)(Vg + gr + (f << 2));
            k4.x *= lk; k4.y *= lk; k4.z *= lk; k4.w *= lk;
            *(float4*)&Ks[r][f << 2] = k4;
            *(float4*)&Vs[r][f << 2] = v4;
        }
        __syncthreads();
        for (int j = 0; j < 64; ++j) {
            float4 ka = *(float4*)&Ks[j][ty << 2];
            float4 vb = *(float4*)&Vs[j][tx << 2];
            float kr[4] = {ka.x, ka.y, ka.z, ka.w};
            float vr[4] = {vb.x, vb.y, vb.z, vb.w};
#pragma unroll
            for (int i = 0; i < 4; i++)
#pragma unroll
                for (int q = 0; q < 4; q++)
                    acc[i][q] = fmaf(kr[i], vr[q], acc[i][q]);
        }
    }

    float* out = Mo + ((size_t)bh * NCH + c) * 4096;
#pragma unroll
    for (int r = 0; r < 4; r++) {
        float4 o = make_float4(acc[r][0], acc[r][1], acc[r][2], acc[r][3]);
        *(float4*)(out + ((ty << 2) + r) * 64 + (tx << 2)) = o;
    }
}

// ------------- pass B: decayed prefix scan of M over chunks -----------------
__global__ __launch_bounds__(1024) void kv_scan_k(
    const float* __restrict__ Mi, float* __restrict__ KVo)
{
    const int bh = blockIdx.x;
    const int h = bh & 15;
    const float s = head_slope(h);
    const float lamc = expf(-s * 128.f);
    const int tid = threadIdx.x;

    float acc[4] = {0.f, 0.f, 0.f, 0.f};
    const size_t base = (size_t)bh * NCH * 4096;
    for (int c = 0; c < NCH; ++c) {
        const size_t cb = base + (size_t)c * 4096;
#pragma unroll
        for (int r = 0; r < 4; ++r) {
            const size_t idx = cb + tid + (r << 10);
            KVo[idx] = acc[r];
            acc[r] = fmaf(lamc, acc[r], Mi[idx]);
        }
    }
}

// ------------- pass C: O = (mask o QK^T) V + lamq o (Q @ KVin) --------------
// dynamic smem layout (floats):
//   dpw[132] | Qt[64][132] | U(Kt[64][132] then Vs[128][68]) | KVs[64][68] | St[128][132]
#define SM_QT 132
#define SM_U  (SM_QT + 64 * 132)
#define SM_KV (SM_U + 8704)
#define SM_ST (SM_KV + 64 * 68)
#define SM_TOTF (SM_ST + 128 * 132)

__global__ __launch_bounds__(256) void attn_chunk_k(
    const float* __restrict__ Qg, const float* __restrict__ Kg,
    const float* __restrict__ Vg, const float* __restrict__ KVi,
    float* __restrict__ Og)
{
    extern __shared__ float sm[];
    float* dpw = sm;
    float* Qt = sm + SM_QT;
    float* Uu = sm + SM_U;
    float* KVs = sm + SM_KV;
    float* St = sm + SM_ST;

    const int c = blockIdx.x, bh = blockIdx.y;
    const int b = bh >> 4, h = bh & 15;
    const int tid = threadIdx.x;
    const float s = head_slope(h);
    if (tid < 129) dpw[tid] = expf(-s * (float)tid);

    const size_t rowbase = (size_t)b * 8192 + (size_t)c * 128;
    const int colbase = h * 64;

    // load Q and K transposed into smem (Qt[d][i], Kt[d][j])
    {
        const int r = tid >> 1;
        const int fb = (tid & 1) * 8;
        const size_t gr = (rowbase + r) * 1024 + colbase;
#pragma unroll
        for (int it = 0; it < 8; ++it) {
            const int f = fb + it;
            float4 q4 = *(const float4*)(Qg + gr + (f << 2));
            float4 k4 = *(const float4*)(Kg + gr + (f << 2));
            const int d0 = f << 2;
            Qt[(d0 + 0) * 132 + r] = q4.x; Qt[(d0 + 1) * 132 + r] = q4.y;
            Qt[(d0 + 2) * 132 + r] = q4.z; Qt[(d0 + 3) * 132 + r] = q4.w;
            Uu[(d0 + 0) * 132 + r] = k4.x; Uu[(d0 + 1) * 132 + r] = k4.y;
            Uu[(d0 + 2) * 132 + r] = k4.z; Uu[(d0 + 3) * 132 + r] = k4.w;
        }
        const float* kvsrc = KVi + ((size_t)bh * NCH + c) * 4096;
#pragma unroll
        for (int it = 0; it < 4; ++it) {
            const int idx = tid + (it << 8);       // float4 index, 0..1023
            float4 v4 = *(const float4*)(kvsrc + (idx << 2));
            const int d = idx >> 4, e4 = (idx & 15) << 2;
            *(float4*)&KVs[d * 68 + e4] = v4;
        }
    }
    __syncthreads();

    const int tx = tid & 15, ty = tid >> 4;

    // phase S: S[i][j] = q_i . k_j
    float sacc[8][8];
#pragma unroll
    for (int i = 0; i < 8; i++)
#pragma unroll
        for (int j = 0; j < 8; j++) sacc[i][j] = 0.f;

    for (int d = 0; d < 64; ++d) {
        float4 a0 = *(float4*)&Qt[d * 132 + (ty << 2)];
        float4 a1 = *(float4*)&Qt[d * 132 + 64 + (ty << 2)];
        float4 b0 = *(float4*)&Uu[d * 132 + (tx << 2)];
        float4 b1 = *(float4*)&Uu[d * 132 + 64 + (tx << 2)];
        float ar[8] = {a0.x, a0.y, a0.z, a0.w, a1.x, a1.y, a1.z, a1.w};
        float br[8] = {b0.x, b0.y, b0.z, b0.w, b1.x, b1.y, b1.z, b1.w};
#pragma unroll
        for (int i = 0; i < 8; i++)
#pragma unroll
            for (int j = 0; j < 8; j++)
                sacc[i][j] = fmaf(ar[i], br[j], sacc[i][j]);
    }

    // write masked S transposed: St[j][i]
#pragma unroll
    for (int jj = 0; jj < 8; jj++) {
        const int j = (jj < 4) ? ((tx << 2) + jj) : (64 + (tx << 2) + jj - 4);
#pragma unroll
        for (int ii = 0; ii < 8; ii++) {
            const int i = (ii < 4) ? ((ty << 2) + ii) : (64 + (ty << 2) + ii - 4);
            const int dlt = i - j;
            St[j * 132 + i] = (dlt >= 0) ? sacc[ii][jj] * dpw[dlt] : 0.f;
        }
    }
    __syncthreads();

    // load V over the Kt region: Vs[j][e], stride 68
    {
        const int r = tid >> 1;
        const int fb = (tid & 1) * 8;
        const size_t gr = (rowbase + r) * 1024 + colbase;
#pragma unroll
        for (int it = 0; it < 8; ++it) {
            const int f = fb + it;
            float4 v4 = *(const float4*)(Vg + gr + (f << 2));
            *(float4*)&Uu[r * 68 + (f << 2)] = v4;
        }
    }
    __syncthreads();

    // phase O
    float oacc[8][4], iacc[8][4];
#pragma unroll
    for (int i = 0; i < 8; i++)
#pragma unroll
        for (int q = 0; q < 4; q++) { oacc[i][q] = 0.f; iacc[i][q] = 0.f; }

    for (int j = 0; j < 128; ++j) {
        float4 s0 = *(float4*)&St[j * 132 + (ty << 2)];
        float4 s1 = *(float4*)&St[j * 132 + 64 + (ty << 2)];
        float4 vv = *(float4*)&Uu[j * 68 + (tx << 2)];
        float sr[8] = {s0.x, s0.y, s0.z, s0.w, s1.x, s1.y, s1.z, s1.w};
        float vr[4] = {vv.x, vv.y, vv.z, vv.w};
#pragma unroll
        for (int i = 0; i < 8; i++)
#pragma unroll
            for (int q = 0; q < 4; q++)
                oacc[i][q] = fmaf(sr[i], vr[q], oacc[i][q]);
    }
    for (int d = 0; d < 64; ++d) {
        float4 q0 = *(float4*)&Qt[d * 132 + (ty << 2)];
        float4 q1 = *(float4*)&Qt[d * 132 + 64 + (ty << 2)];
        float4 kv = *(float4*)&KVs[d * 68 + (tx << 2)];
        float qr[8] = {q0.x, q0.y, q0.z, q0.w, q1.x, q1.y, q1.z, q1.w};
        float kr[4] = {kv.x, kv.y, kv.z, kv.w};
#pragma unroll
        for (int i = 0; i < 8; i++)
#pragma unroll
            for (int q = 0; q < 4; q++)
                iacc[i][q] = fmaf(qr[i], kr[q], iacc[i][q]);
    }

#pragma unroll
    for (int ii = 0; ii < 8; ii++) {
        const int i = (ii < 4) ? ((ty << 2) + ii) : (64 + (ty << 2) + ii - 4);
        const float lam = dpw[i + 1];
        float4 o;
        o.x = fmaf(lam, iacc[ii][0], oacc[ii][0]);
        o.y = fmaf(lam, iacc[ii][1], oacc[ii][1]);
        o.z = fmaf(lam, iacc[ii][2], oacc[ii][2]);
        o.w = fmaf(lam, iacc[ii][3], oacc[ii][3]);
        *(float4*)(Og + (rowbase + i) * 1024 + colbase + (tx << 2)) = o;
    }
}

// ------------- LayerNorm * gate (in place on O) ----------------------------
__global__ __launch_bounds__(256) void ln_gate_k(
    const float* __restrict__ O, const float* __restrict__ G,
    const float* __restrict__ gamma, const float* __restrict__ beta,
    float* __restrict__ OG)
{
    __shared__ float red[2][8];
    const int row = blockIdx.x, tid = threadIdx.x;
    const size_t base = (size_t)row * 1024 + (tid << 2);
    float4 v = *(const float4*)(O + base);
    float sum = v.x + v.y + v.z + v.w;
    float sq = v.x * v.x + v.y * v.y + v.z * v.z + v.w * v.w;
#pragma unroll
    for (int o = 16; o > 0; o >>= 1) {
        sum += __shfl_xor_sync(0xffffffff, sum, o);
        sq += __shfl_xor_sync(0xffffffff, sq, o);
    }
    if ((tid & 31) == 0) { red[0][tid >> 5] = sum; red[1][tid >> 5] = sq; }
    __syncthreads();
    float ts = 0.f, tq = 0.f;
#pragma unroll
    for (int w = 0; w < 8; w++) { ts += red[0][w]; tq += red[1][w]; }
    const float mu = ts * (1.f / 1024.f);
    const float var = tq * (1.f / 1024.f) - mu * mu;
    const float rstd = rsqrtf(var + 1e-5f);

    float4 g4 = *(const float4*)(gamma + (tid << 2));
    float4 b4 = *(const float4*)(beta + (tid << 2));
    float4 gt = *(const float4*)(G + base);
    float4 o;
    o.x = ((v.x - mu) * rstd * g4.x + b4.x) * gt.x;
    o.y = ((v.y - mu) * rstd * g4.y + b4.y) * gt.y;
    o.z = ((v.z - mu) * rstd * g4.z + b4.z) * gt.z;
    o.w = ((v.w - mu) * rstd * g4.w + b4.w) * gt.w;
    *(float4*)(OG + base) = o;
}

// ---------------------------------------------------------------------------
extern "C" void kernel_launch(void* const* d_in, const int* in_sizes, int n_in,
                              void* d_out, int out_size)
{
    const float* x     = (const float*)d_in[0];
    const float* Wq    = (const float*)d_in[1];
    const float* Wk    = (const float*)d_in[2];
    const float* Wv    = (const float*)d_in[3];
    const float* Wo    = (const float*)d_in[4];
    const float* gamma = (const float*)d_in[5];
    const float* beta  = (const float*)d_in[6];
    const float* Wg1   = (const float*)d_in[7];
    const float* Wg2   = (const float*)d_in[8];
    float* out = (float*)d_out;

    void *pQ, *pK, *pV, *pO, *pGATE, *pG1, *pM, *pKV;
    cudaGetSymbolAddress(&pQ, gQ);
    cudaGetSymbolAddress(&pK, gK);
    cudaGetSymbolAddress(&pV, gV);
    cudaGetSymbolAddress(&pO, gO);
    cudaGetSymbolAddress(&pGATE, gGATE);
    cudaGetSymbolAddress(&pG1, gG1);
    cudaGetSymbolAddress(&pM, gM);
    cudaGetSymbolAddress(&pKV, gKV);
    float* Q = (float*)pQ;  float* Kb = (float*)pK;  float* Vb = (float*)pV;
    float* Ob = (float*)pO; float* GATE = (float*)pGATE; float* G1 = (float*)pG1;
    float* Mb = (float*)pM; float* KVb = (float*)pKV;

    const size_t smemC = (size_t)SM_TOTF * sizeof(float);   // ~150.5 KB
    cudaFuncSetAttribute(attn_chunk_k,
                         cudaFuncAttributeMaxDynamicSharedMemorySize, (int)smemC);

    dim3 tB(256);
    dim3 gBig(EDIM / 128, MDIM / 128);     // (8, 128)

    // projections
    sgemm_k<1><<<gBig, tB>>>(x, Wq, Q, MDIM, EDIM, EDIM);
    sgemm_k<1><<<gBig, tB>>>(x, Wk, Kb, MDIM, EDIM, EDIM);
    sgemm_k<1><<<gBig, tB>>>(x, Wv, Vb, MDIM, EDIM, EDIM);

    // gate path
    sgemm_k<0><<<dim3(1, MDIM / 128), tB>>>(x, Wg1, G1, MDIM, DH, EDIM);
    sgemm_k<2><<<gBig, tB>>>(G1, Wg2, GATE, MDIM, EDIM, DH);

    // attention
    chunk_kv_k<<<dim3(NCH, BHN), 256>>>(Kb, Vb, Mb);
    kv_scan_k<<<BHN, 1024>>>(Mb, KVb);
    attn_chunk_k<<<dim3(NCH, BHN), 256, smemC>>>(Q, Kb, Vb, KVb, Ob);

    // layernorm * gate (in place), final projection
    ln_gate_k<<<MDIM, 256>>>(Ob, GATE, gamma, beta, Ob);
    sgemm_k<0><<<gBig, tB>>>(Ob, Wo, out, MDIM, EDIM, EDIM);
}

// round 2
// speedup vs baseline: 2.6583x; 2.6583x over previous
#include <cuda_runtime.h>
#include <math.h>
#include <stdint.h>

// Problem constants
#define MDIM 16384          // B*N = 2*8192 rows
#define EDIM 1024           // embed
#define HN   16             // heads
#define DH   64             // head dim
#define NCH  64             // chunks per sequence (8192/128)
#define BHN  32             // B*H

// ---------------- scratch (device globals; no allocation allowed) ------------
__device__ float gQ[MDIM * EDIM];
__device__ float gK[MDIM * EDIM];
__device__ float gV[MDIM * EDIM];
__device__ float gO[MDIM * EDIM];
__device__ float gGATE[MDIM * EDIM];
__device__ float gG1[MDIM * DH];
__device__ float gM[BHN * NCH * DH * DH];
__device__ float gKV[BHN * NCH * DH * DH];

__device__ __forceinline__ float head_slope(int h) {
    return exp2f(-0.5f * (float)(h + 1)) * 1.00001f;
}

template <int EPI>
__device__ __forceinline__ float epilogue(float v) {
    if (EPI == 1) return v / (1.f + expf(-v));      // silu
    if (EPI == 2) return 1.f / (1.f + expf(-v));    // sigmoid
    return v;
}

// =================== TF32 tensor-core GEMM =================================
// C = epi(A @ B), row-major. 128x128x32 tile, 256 thr (8 warps 2x4),
// warp tile 64x32 via m16n8k8 tf32 mma. cp.async 2-stage pipeline.
#define BM 128
#define BN 128
#define BK 32
#define ASTR 36     // As[m][k] stride (floats)  -> frag banks 4*gid+tg (perm)
#define BSTR 136    // Bs[k][n] stride (floats)  -> frag banks 8*tg+gid (perm)
#define STAGE_F (BM * ASTR + BK * BSTR)   // 4608 + 4352 = 8960 floats
#define TGEMM_SMEM (2 * STAGE_F * 4)      // 71680 bytes

__device__ __forceinline__ uint32_t cvt_tf32(float x) {
    uint32_t r;
    asm("cvt.rna.tf32.f32 %0, %1;" : "=r"(r) : "f"(x));
    return r;
}

template <int EPI>
__global__ __launch_bounds__(256) void tgemm_k(
    const float* __restrict__ A, const float* __restrict__ B,
    float* __restrict__ C, int M, int N, int K)
{
    extern __shared__ float sm[];
    const int tid = threadIdx.x;
    const int lane = tid & 31, wid = tid >> 5;
    const int gid = lane >> 2, tg = lane & 3;
    const int wm = (wid >> 2) * 64;        // warp M offset (0 or 64)
    const int wn = (wid & 3) * 32;         // warp N offset (0..96)
    const int bm = blockIdx.y << 7, bn = blockIdx.x << 7;

    const uint32_t smu = (uint32_t)__cvta_generic_to_shared(sm);

    // loader indices
    const int ar = tid >> 3, ac = (tid & 7) << 2;         // A: 128x8 float4
    const int br = tid >> 5, bc = (tid & 31) << 2;        // B: 32x32 float4 (4 iters)

    const int KT = K / BK;

    // ---- async copy issue for k-tile kt into stage s ----
    auto issue = [&](int kt, int s) {
        const uint32_t sa = smu + (uint32_t)(s * STAGE_F) * 4u;
        const uint32_t sb = sa + (uint32_t)(BM * ASTR) * 4u;
        // A: each thread 1 float4 per 2 rows? 128 rows * 8 f4 = 1024 slots / 256 = 4
#pragma unroll
        for (int i = 0; i < 4; i++) {
            const int row = ar + i * 32;                  // tid>>3 in 0..31, 4 iters -> 0..127
            const float* src = A + (size_t)(bm + row) * K + kt * BK + ac;
            const uint32_t dst = sa + (uint32_t)(row * ASTR + ac) * 4u;
            asm volatile("cp.async.cg.shared.global [%0], [%1], 16;\n"
                         :: "r"(dst), "l"(src));
        }
#pragma unroll
        for (int i = 0; i < 4; i++) {
            const int row = br + i * 8;                   // 0..31
            const int col = bc;                           // 0..124
            if (bn + col < N) {
                const float* src = B + (size_t)(kt * BK + row) * N + bn + col;
                const uint32_t dst = sb + (uint32_t)(row * BSTR + col) * 4u;
                asm volatile("cp.async.cg.shared.global [%0], [%1], 16;\n"
                             :: "r"(dst), "l"(src));
            }
        }
        asm volatile("cp.async.commit_group;\n" ::);
    };

    float acc[4][4][4];
#pragma unroll
    for (int i = 0; i < 4; i++)
#pragma unroll
        for (int j = 0; j < 4; j++)
#pragma unroll
            for (int q = 0; q < 4; q++) acc[i][j][q] = 0.f;

    issue(0, 0);
    issue(1, 1);
    asm volatile("cp.async.wait_group 1;\n" ::);
    __syncthreads();

    for (int kt = 0; kt < KT; ++kt) {
        const int s = kt & 1;
        const float* sA = sm + s * STAGE_F;
        const float* sB = sA + BM * ASTR;

#pragma unroll
        for (int ks = 0; ks < 4; ++ks) {
            const int k0 = ks * 8;
            uint32_t af[4][4], bf[4][2];
#pragma unroll
            for (int mt = 0; mt < 4; mt++) {
                const int m = wm + mt * 16 + gid;
                af[mt][0] = cvt_tf32(sA[m * ASTR + k0 + tg]);
                af[mt][1] = cvt_tf32(sA[(m + 8) * ASTR + k0 + tg]);
                af[mt][2] = cvt_tf32(sA[m * ASTR + k0 + tg + 4]);
                af[mt][3] = cvt_tf32(sA[(m + 8) * ASTR + k0 + tg + 4]);
            }
#pragma unroll
            for (int nt = 0; nt < 4; nt++) {
                const int n = wn + nt * 8 + gid;
                bf[nt][0] = cvt_tf32(sB[(k0 + tg) * BSTR + n]);
                bf[nt][1] = cvt_tf32(sB[(k0 + tg + 4) * BSTR + n]);
            }
#pragma unroll
            for (int mt = 0; mt < 4; mt++)
#pragma unroll
                for (int nt = 0; nt < 4; nt++) {
                    asm volatile(
                        "mma.sync.aligned.m16n8k8.row.col.f32.tf32.tf32.f32 "
                        "{%0,%1,%2,%3}, {%4,%5,%6,%7}, {%8,%9}, {%0,%1,%2,%3};\n"
                        : "+f"(acc[mt][nt][0]), "+f"(acc[mt][nt][1]),
                          "+f"(acc[mt][nt][2]), "+f"(acc[mt][nt][3])
                        : "r"(af[mt][0]), "r"(af[mt][1]), "r"(af[mt][2]), "r"(af[mt][3]),
                          "r"(bf[nt][0]), "r"(bf[nt][1]));
                }
        }

        __syncthreads();                      // everyone done reading stage s
        if (kt + 2 < KT) {
            issue(kt + 2, s);
            asm volatile("cp.async.wait_group 1;\n" ::);
        } else {
            asm volatile("cp.async.wait_group 0;\n" ::);
        }
        __syncthreads();
    }

    // epilogue
#pragma unroll
    for (int mt = 0; mt < 4; mt++) {
#pragma unroll
        for (int nt = 0; nt < 4; nt++) {
            const int r0 = bm + wm + mt * 16 + gid;
            const int c = bn + wn + nt * 8 + 2 * tg;
            if (c < N) {
                float2 lo, hi;
                lo.x = epilogue<EPI>(acc[mt][nt][0]);
                lo.y = epilogue<EPI>(acc[mt][nt][1]);
                hi.x = epilogue<EPI>(acc[mt][nt][2]);
                hi.y = epilogue<EPI>(acc[mt][nt][3]);
                *(float2*)(C + (size_t)r0 * N + c) = lo;
                *(float2*)(C + (size_t)(r0 + 8) * N + c) = hi;
            }
        }
    }
}

// ------------- pass A: per-chunk M = K^T diag(lamk) V  [64x64] --------------
__global__ __launch_bounds__(256) void chunk_kv_k(
    const float* __restrict__ Kg, const float* __restrict__ Vg,
    float* __restrict__ Mo)
{
    __shared__ float Ks[64][68];
    __shared__ float Vs[64][68];
    __shared__ float dpw[132];

    const int c = blockIdx.x, bh = blockIdx.y;
    const int b = bh >> 4, h = bh & 15;
    const int tid = threadIdx.x;
    const float s = head_slope(h);
    if (tid < 129) dpw[tid] = expf(-s * (float)tid);
    __syncthreads();

    const int tx = tid & 15, ty = tid >> 4;
    float acc[4][4];
#pragma unroll
    for (int i = 0; i < 4; i++)
#pragma unroll
        for (int j = 0; j < 4; j++) acc[i][j] = 0.f;

    const size_t rowbase = (size_t)b * 8192 + (size_t)c * 128;
    const int colbase = h * 64;

    for (int half = 0; half < 2; ++half) {
        if (half) __syncthreads();
        const int r = tid >> 2;
        const int f0 = tid & 3;
        const int jg = (half << 6) + r;
        const float lk = dpw[127 - jg];
        const size_t gr = (rowbase + jg) * 1024 + colbase;
#pragma unroll
        for (int it = 0; it < 4; ++it) {
            const int f = f0 + (it << 2);
            float4 k4 = *(const float4*)(Kg + gr + (f << 2));
            float4 v4 = *(const float4*)(Vg + gr + (f << 2));
            k4.x *= lk; k4.y *= lk; k4.z *= lk; k4.w *= lk;
            *(float4*)&Ks[r][f << 2] = k4;
            *(float4*)&Vs[r][f << 2] = v4;
        }
        __syncthreads();
        for (int j = 0; j < 64; ++j) {
            float4 ka = *(float4*)&Ks[j][ty << 2];
            float4 vb = *(float4*)&Vs[j][tx << 2];
            float kr[4] = {ka.x, ka.y, ka.z, ka.w};
            float vr[4] = {vb.x, vb.y, vb.z, vb.w};
#pragma unroll
            for (int i = 0; i < 4; i++)
#pragma unroll
                for (int q = 0; q < 4; q++)
                    acc[i][q] = fmaf(kr[i], vr[q], acc[i][q]);
        }
    }

    float* out = Mo + ((size_t)bh * NCH + c) * 4096;
#pragma unroll
    for (int r = 0; r < 4; r++) {
        float4 o = make_float4(acc[r][0], acc[r][1], acc[r][2], acc[r][3]);
        *(float4*)(out + ((ty << 2) + r) * 64 + (tx << 2)) = o;
    }
}

// ------------- pass B: decayed prefix scan of M over chunks -----------------
__global__ __launch_bounds__(1024) void kv_scan_k(
    const float* __restrict__ Mi, float* __restrict__ KVo)
{
    const int bh = blockIdx.x;
    const int h = bh & 15;
    const float s = head_slope(h);
    const float lamc = expf(-s * 128.f);
    const int tid = threadIdx.x;

    float acc[4] = {0.f, 0.f, 0.f, 0.f};
    const size_t base = (size_t)bh * NCH * 4096;
    for (int c = 0; c < NCH; ++c) {
        const size_t cb = base + (size_t)c * 4096;
#pragma unroll
        for (int r = 0; r < 4; ++r) {
            const size_t idx = cb + tid + (r << 10);
            KVo[idx] = acc[r];
            acc[r] = fmaf(lamc, acc[r], Mi[idx]);
        }
    }
}

// ------------- pass C: O = (mask o QK^T) V + lamq o (Q @ KVin) --------------
#define SM_QT 132
#define SM_U  (SM_QT + 64 * 132)
#define SM_KV (SM_U + 8704)
#define SM_ST (SM_KV + 64 * 68)
#define SM_TOTF (SM_ST + 128 * 132)

__global__ __launch_bounds__(256) void attn_chunk_k(
    const float* __restrict__ Qg, const float* __restrict__ Kg,
    const float* __restrict__ Vg, const float* __restrict__ KVi,
    float* __restrict__ Og)
{
    extern __shared__ float smd[];
    float* dpw = smd;
    float* Qt = smd + SM_QT;
    float* Uu = smd + SM_U;
    float* KVs = smd + SM_KV;
    float* St = smd + SM_ST;

    const int c = blockIdx.x, bh = blockIdx.y;
    const int b = bh >> 4, h = bh & 15;
    const int tid = threadIdx.x;
    const float s = head_slope(h);
    if (tid < 129) dpw[tid] = expf(-s * (float)tid);

    const size_t rowbase = (size_t)b * 8192 + (size_t)c * 128;
    const int colbase = h * 64;

    {
        const int r = tid >> 1;
        const int fb = (tid & 1) * 8;
        const size_t gr = (rowbase + r) * 1024 + colbase;
#pragma unroll
        for (int it = 0; it < 8; ++it) {
            const int f = fb + it;
            float4 q4 = *(const float4*)(Qg + gr + (f << 2));
            float4 k4 = *(const float4*)(Kg + gr + (f << 2));
            const int d0 = f << 2;
            Qt[(d0 + 0) * 132 + r] = q4.x; Qt[(d0 + 1) * 132 + r] = q4.y;
            Qt[(d0 + 2) * 132 + r] = q4.z; Qt[(d0 + 3) * 132 + r] = q4.w;
            Uu[(d0 + 0) * 132 + r] = k4.x; Uu[(d0 + 1) * 132 + r] = k4.y;
            Uu[(d0 + 2) * 132 + r] = k4.z; Uu[(d0 + 3) * 132 + r] = k4.w;
        }
        const float* kvsrc = KVi + ((size_t)bh * NCH + c) * 4096;
#pragma unroll
        for (int it = 0; it < 4; ++it) {
            const int idx = tid + (it << 8);
            float4 v4 = *(const float4*)(kvsrc + (idx << 2));
            const int d = idx >> 4, e4 = (idx & 15) << 2;
            *(float4*)&KVs[d * 68 + e4] = v4;
        }
    }
    __syncthreads();

    const int tx = tid & 15, ty = tid >> 4;

    float sacc[8][8];
#pragma unroll
    for (int i = 0; i < 8; i++)
#pragma unroll
        for (int j = 0; j < 8; j++) sacc[i][j] = 0.f;

    for (int d = 0; d < 64; ++d) {
        float4 a0 = *(float4*)&Qt[d * 132 + (ty << 2)];
        float4 a1 = *(float4*)&Qt[d * 132 + 64 + (ty << 2)];
        float4 b0 = *(float4*)&Uu[d * 132 + (tx << 2)];
        float4 b1 = *(float4*)&Uu[d * 132 + 64 + (tx << 2)];
        float ar[8] = {a0.x, a0.y, a0.z, a0.w, a1.x, a1.y, a1.z, a1.w};
        float br[8] = {b0.x, b0.y, b0.z, b0.w, b1.x, b1.y, b1.z, b1.w};
#pragma unroll
        for (int i = 0; i < 8; i++)
#pragma unroll
            for (int j = 0; j < 8; j++)
                sacc[i][j] = fmaf(ar[i], br[j], sacc[i][j]);
    }

#pragma unroll
    for (int jj = 0; jj < 8; jj++) {
        const int j = (jj < 4) ? ((tx << 2) + jj) : (64 + (tx << 2) + jj - 4);
#pragma unroll
        for (int ii = 0; ii < 8; ii++) {
            const int i = (ii < 4) ? ((ty << 2) + ii) : (64 + (ty << 2) + ii - 4);
            const int dlt = i - j;
            St[j * 132 + i] = (dlt >= 0) ? sacc[ii][jj] * dpw[dlt] : 0.f;
        }
    }
    __syncthreads();

    {
        const int r = tid >> 1;
        const int fb = (tid & 1) * 8;
        const size_t gr = (rowbase + r) * 1024 + colbase;
#pragma unroll
        for (int it = 0; it < 8; ++it) {
            const int f = fb + it;
            float4 v4 = *(const float4*)(Vg + gr + (f << 2));
            *(float4*)&Uu[r * 68 + (f << 2)] = v4;
        }
    }
    __syncthreads();

    float oacc[8][4], iacc[8][4];
#pragma unroll
    for (int i = 0; i < 8; i++)
#pragma unroll
        for (int q = 0; q < 4; q++) { oacc[i][q] = 0.f; iacc[i][q] = 0.f; }

    for (int j = 0; j < 128; ++j) {
        float4 s0 = *(float4*)&St[j * 132 + (ty << 2)];
        float4 s1 = *(float4*)&St[j * 132 + 64 + (ty << 2)];
        float4 vv = *(float4*)&Uu[j * 68 + (tx << 2)];
        float sr[8] = {s0.x, s0.y, s0.z, s0.w, s1.x, s1.y, s1.z, s1.w};
        float vr[4] = {vv.x, vv.y, vv.z, vv.w};
#pragma unroll
        for (int i = 0; i < 8; i++)
#pragma unroll
            for (int q = 0; q < 4; q++)
                oacc[i][q] = fmaf(sr[i], vr[q], oacc[i][q]);
    }
    for (int d = 0; d < 64; ++d) {
        float4 q0 = *(float4*)&Qt[d * 132 + (ty << 2)];
        float4 q1 = *(float4*)&Qt[d * 132 + 64 + (ty << 2)];
        float4 kv = *(float4*)&KVs[d * 68 + (tx << 2)];
        float qr[8] = {q0.x, q0.y, q0.z, q0.w, q1.x, q1.y, q1.z, q1.w};
        float kr[4] = {kv.x, kv.y, kv.z, kv.w};
#pragma unroll
        for (int i = 0; i < 8; i++)
#pragma unroll
            for (int q = 0; q < 4; q++)
                iacc[i][q] = fmaf(qr[i], kr[q], iacc[i][q]);
    }

#pragma unroll
    for (int ii = 0; ii < 8; ii++) {
        const int i = (ii < 4) ? ((ty << 2) + ii) : (64 + (ty << 2) + ii - 4);
        const float lam = dpw[i + 1];
        float4 o;
        o.x = fmaf(lam, iacc[ii][0], oacc[ii][0]);
        o.y = fmaf(lam, iacc[ii][1], oacc[ii][1]);
        o.z = fmaf(lam, iacc[ii][2], oacc[ii][2]);
        o.w = fmaf(lam, iacc[ii][3], oacc[ii][3]);
        *(float4*)(Og + (rowbase + i) * 1024 + colbase + (tx << 2)) = o;
    }
}

// ------------- LayerNorm * gate (in place on O) ----------------------------
__global__ __launch_bounds__(256) void ln_gate_k(
    const float* __restrict__ O, const float* __restrict__ G,
    const float* __restrict__ gamma, const float* __restrict__ beta,
    float* __restrict__ OG)
{
    __shared__ float red[2][8];
    const int row = blockIdx.x, tid = threadIdx.x;
    const size_t base = (size_t)row * 1024 + (tid << 2);
    float4 v = *(const float4*)(O + base);
    float sum = v.x + v.y + v.z + v.w;
    float sq = v.x * v.x + v.y * v.y + v.z * v.z + v.w * v.w;
#pragma unroll
    for (int o = 16; o > 0; o >>= 1) {
        sum += __shfl_xor_sync(0xffffffff, sum, o);
        sq += __shfl_xor_sync(0xffffffff, sq, o);
    }
    if ((tid & 31) == 0) { red[0][tid >> 5] = sum; red[1][tid >> 5] = sq; }
    __syncthreads();
    float ts = 0.f, tq = 0.f;
#pragma unroll
    for (int w = 0; w < 8; w++) { ts += red[0][w]; tq += red[1][w]; }
    const float mu = ts * (1.f / 1024.f);
    const float var = tq * (1.f / 1024.f) - mu * mu;
    const float rstd = rsqrtf(var + 1e-5f);

    float4 g4 = *(const float4*)(gamma + (tid << 2));
    float4 b4 = *(const float4*)(beta + (tid << 2));
    float4 gt = *(const float4*)(G + base);
    float4 o;
    o.x = ((v.x - mu) * rstd * g4.x + b4.x) * gt.x;
    o.y = ((v.y - mu) * rstd * g4.y + b4.y) * gt.y;
    o.z = ((v.z - mu) * rstd * g4.z + b4.z) * gt.z;
    o.w = ((v.w - mu) * rstd * g4.w + b4.w) * gt.w;
    *(float4*)(OG + base) = o;
}

// ---------------------------------------------------------------------------
extern "C" void kernel_launch(void* const* d_in, const int* in_sizes, int n_in,
                              void* d_out, int out_size)
{
    const float* x     = (const float*)d_in[0];
    const float* Wq    = (const float*)d_in[1];
    const float* Wk    = (const float*)d_in[2];
    const float* Wv    = (const float*)d_in[3];
    const float* Wo    = (const float*)d_in[4];
    const float* gamma = (const float*)d_in[5];
    const float* beta  = (const float*)d_in[6];
    const float* Wg1   = (const float*)d_in[7];
    const float* Wg2   = (const float*)d_in[8];
    float* out = (float*)d_out;

    void *pQ, *pK, *pV, *pO, *pGATE, *pG1, *pM, *pKV;
    cudaGetSymbolAddress(&pQ, gQ);
    cudaGetSymbolAddress(&pK, gK);
    cudaGetSymbolAddress(&pV, gV);
    cudaGetSymbolAddress(&pO, gO);
    cudaGetSymbolAddress(&pGATE, gGATE);
    cudaGetSymbolAddress(&pG1, gG1);
    cudaGetSymbolAddress(&pM, gM);
    cudaGetSymbolAddress(&pKV, gKV);
    float* Q = (float*)pQ;  float* Kb = (float*)pK;  float* Vb = (float*)pV;
    float* Ob = (float*)pO; float* GATE = (float*)pGATE; float* G1 = (float*)pG1;
    float* Mb = (float*)pM; float* KVb = (float*)pKV;

    const size_t smemC = (size_t)SM_TOTF * sizeof(float);
    cudaFuncSetAttribute(attn_chunk_k,
                         cudaFuncAttributeMaxDynamicSharedMemorySize, (int)smemC);
    cudaFuncSetAttribute(tgemm_k<0>,
                         cudaFuncAttributeMaxDynamicSharedMemorySize, TGEMM_SMEM);
    cudaFuncSetAttribute(tgemm_k<1>,
                         cudaFuncAttributeMaxDynamicSharedMemorySize, TGEMM_SMEM);
    cudaFuncSetAttribute(tgemm_k<2>,
                         cudaFuncAttributeMaxDynamicSharedMemorySize, TGEMM_SMEM);

    dim3 tB(256);
    dim3 gBig(EDIM / 128, MDIM / 128);     // (8, 128)

    // projections (tf32 tensor cores, silu epilogue)
    tgemm_k<1><<<gBig, tB, TGEMM_SMEM>>>(x, Wq, Q, MDIM, EDIM, EDIM);
    tgemm_k<1><<<gBig, tB, TGEMM_SMEM>>>(x, Wk, Kb, MDIM, EDIM, EDIM);
    tgemm_k<1><<<gBig, tB, TGEMM_SMEM>>>(x, Wv, Vb, MDIM, EDIM, EDIM);

    // gate path
    tgemm_k<0><<<dim3(1, MDIM / 128), tB, TGEMM_SMEM>>>(x, Wg1, G1, MDIM, DH, EDIM);
    tgemm_k<2><<<gBig, tB, TGEMM_SMEM>>>(G1, Wg2, GATE, MDIM, EDIM, DH);

    // attention (fp32)
    chunk_kv_k<<<dim3(NCH, BHN), 256>>>(Kb, Vb, Mb);
    kv_scan_k<<<BHN, 1024>>>(Mb, KVb);
    attn_chunk_k<<<dim3(NCH, BHN), 256, smemC>>>(Q, Kb, Vb, KVb, Ob);

    // layernorm * gate (in place), final projection
    ln_gate_k<<<MDIM, 256>>>(Ob, GATE, gamma, beta, Ob);
    tgemm_k<0><<<gBig, tB, TGEMM_SMEM>>>(Ob, Wo, out, MDIM, EDIM, EDIM);
}

// round 8
// speedup vs baseline: 2.7517x; 1.0351x over previous
#include <cuda_runtime.h>
#include <math.h>
#include <stdint.h>

// Problem constants
#define MDIM 16384          // B*N = 2*8192 rows
#define EDIM 1024           // embed
#define DH   64             // head dim
#define NCH  64             // chunks per sequence (8192/128)
#define BHN  32             // B*H

// ---------------- scratch (device globals) ----------------------------------
__device__ float gQ[MDIM * EDIM];
__device__ float gK[MDIM * EDIM];
__device__ float gV[MDIM * EDIM];
__device__ float gO[MDIM * EDIM];
__device__ float gGATE[MDIM * EDIM];
__device__ float gG1[MDIM * DH];
__device__ float gM[BHN * NCH * DH * DH];
__device__ float gKV[BHN * NCH * DH * DH];
__device__ float gXR[MDIM * EDIM];
__device__ float gWqR[EDIM * EDIM];
__device__ float gWkR[EDIM * EDIM];
__device__ float gWvR[EDIM * EDIM];
__device__ float gWoR[EDIM * EDIM];
__device__ float gWg1R[EDIM * DH];
__device__ float gWg2R[DH * EDIM];

__device__ __forceinline__ float head_slope(int h) {
    return exp2f(-0.5f * (float)(h + 1)) * 1.00001f;
}

template <int EPI>
__device__ __forceinline__ float epilogue(float v) {
    if (EPI == 1) return v / (1.f + expf(-v));      // silu
    if (EPI == 2) return 1.f / (1.f + expf(-v));    // sigmoid
    return v;
}

__device__ __forceinline__ uint32_t cvt_tf32(float x) {
    uint32_t r;
    asm("cvt.rna.tf32.f32 %0, %1;" : "=r"(r) : "f"(x));
    return r;
}
__device__ __forceinline__ float round_tf32(float x) {
    return __uint_as_float(cvt_tf32(x));
}

#define MMA_TF32(acc, a0, a1, a2, a3, b0, b1) \
    asm volatile( \
        "mma.sync.aligned.m16n8k8.row.col.f32.tf32.tf32.f32 " \
        "{%0,%1,%2,%3}, {%4,%5,%6,%7}, {%8,%9}, {%0,%1,%2,%3};\n" \
        : "+f"((acc)[0]), "+f"((acc)[1]), "+f"((acc)[2]), "+f"((acc)[3]) \
        : "r"(a0), "r"(a1), "r"(a2), "r"(a3), "r"(b0), "r"(b1))

__device__ __forceinline__ void cpa_wait(int keep) {
    if (keep <= 0)      asm volatile("cp.async.wait_group 0;" ::);
    else                asm volatile("cp.async.wait_group 1;" ::);
}

// =================== TF32 mma.sync GEMM (pre-rounded inputs) ================
// C = epi(A @ B). A[M,K], B[K,N] row-major, both already tf32-rounded.
// 128 x BN_ x 32 tile, 256 thr (8 warps 2x4), warp tile 64 x (BN_/4),
// NT = BN_/32 n-tiles per warp. 3-stage cp.async, 1 sync/iter.
#define ASTR 36
template <int EPI, int BN_, bool RND>
__global__ __launch_bounds__(256) void tgemm2_k(
    const float* __restrict__ A, const float* __restrict__ B,
    float* __restrict__ C, int M, int N, int K)
{
    constexpr int BSTR = BN_ + 8;
    constexpr int SA_F = 128 * ASTR;
    constexpr int STAGE_F = SA_F + 32 * BSTR;
    constexpr int TPR = BN_ / 4;            // threads per B row (float4)
    constexpr int BITER = (32 * TPR) / 256;
    constexpr int NT = BN_ / 32;            // n-tiles (m16n8) per warp

    extern __shared__ float sm[];
    const int tid = threadIdx.x;
    const int lane = tid & 31, wid = tid >> 5;
    const int gid = lane >> 2, tg = lane & 3;
    const int wm = (wid >> 2) * 64;
    const int wn = (wid & 3) * (BN_ / 4);
    const int bm = blockIdx.y << 7;
    const int bn = blockIdx.x * BN_;
    const uint32_t smu = (uint32_t)__cvta_generic_to_shared(sm);
    const int KT = K >> 5;

    auto fill = [&](int kt) {
        const uint32_t sa = smu + (uint32_t)((kt % 3) * STAGE_F) * 4u;
        const uint32_t sb = sa + (uint32_t)SA_F * 4u;
#pragma unroll
        for (int i = 0; i < 4; i++) {
            const int idx = tid + (i << 8);
            const int row = idx >> 3, col = (idx & 7) << 2;
            const float* src = A + (size_t)(bm + row) * K + (kt << 5) + col;
            asm volatile("cp.async.cg.shared.global [%0], [%1], 16;"
                         :: "r"(sa + (uint32_t)(row * ASTR + col) * 4u), "l"(src));
        }
#pragma unroll
        for (int i = 0; i < BITER; i++) {
            const int idx = tid + (i << 8);
            const int row = idx / TPR, col = (idx % TPR) << 2;
            const float* src = B + (size_t)((kt << 5) + row) * N + bn + col;
            asm volatile("cp.async.cg.shared.global [%0], [%1], 16;"
                         :: "r"(sb + (uint32_t)(row * BSTR + col) * 4u), "l"(src));
        }
        asm volatile("cp.async.commit_group;");
    };

    float acc[4][NT][4];
#pragma unroll
    for (int i = 0; i < 4; i++)
#pragma unroll
        for (int j = 0; j < NT; j++)
#pragma unroll
            for (int q = 0; q < 4; q++) acc[i][j][q] = 0.f;

    fill(0);
    if (KT > 1) fill(1);

    for (int kt = 0; kt < KT; ++kt) {
        cpa_wait((kt + 1 < KT) ? 1 : 0);
        __syncthreads();
        if (kt + 2 < KT) fill(kt + 2);

        const float* sA = sm + (kt % 3) * STAGE_F;
        const float* sB = sA + SA_F;
#pragma unroll
        for (int ks = 0; ks < 4; ++ks) {
            const int k0 = ks * 8;
            uint32_t af[4][4], bf[NT][2];
#pragma unroll
            for (int mt = 0; mt < 4; mt++) {
                const int m = wm + mt * 16 + gid;
                af[mt][0] = __float_as_uint(sA[m * ASTR + k0 + tg]);
                af[mt][1] = __float_as_uint(sA[(m + 8) * ASTR + k0 + tg]);
                af[mt][2] = __float_as_uint(sA[m * ASTR + k0 + tg + 4]);
                af[mt][3] = __float_as_uint(sA[(m + 8) * ASTR + k0 + tg + 4]);
            }
#pragma unroll
            for (int nt = 0; nt < NT; nt++) {
                const int n = wn + nt * 8 + gid;
                bf[nt][0] = __float_as_uint(sB[(k0 + tg) * BSTR + n]);
                bf[nt][1] = __float_as_uint(sB[(k0 + tg + 4) * BSTR + n]);
            }
#pragma unroll
            for (int mt = 0; mt < 4; mt++)
#pragma unroll
                for (int nt = 0; nt < NT; nt++)
                    MMA_TF32(acc[mt][nt], af[mt][0], af[mt][1], af[mt][2], af[mt][3],
                             bf[nt][0], bf[nt][1]);
        }
    }

#pragma unroll
    for (int mt = 0; mt < 4; mt++) {
#pragma unroll
        for (int nt = 0; nt < NT; nt++) {
            const int r0 = bm + wm + mt * 16 + gid;
            const int c = bn + wn + nt * 8 + 2 * tg;
            float2 lo, hi;
            lo.x = epilogue<EPI>(acc[mt][nt][0]);
            lo.y = epilogue<EPI>(acc[mt][nt][1]);
            hi.x = epilogue<EPI>(acc[mt][nt][2]);
            hi.y = epilogue<EPI>(acc[mt][nt][3]);
            if (RND) {
                lo.x = round_tf32(lo.x); lo.y = round_tf32(lo.y);
                hi.x = round_tf32(hi.x); hi.y = round_tf32(hi.y);
            }
            *(float2*)(C + (size_t)r0 * N + c) = lo;
            *(float2*)(C + (size_t)(r0 + 8) * N + c) = hi;
        }
    }
}

// ---------------- prep: round to tf32 (rna) --------------------------------
__global__ __launch_bounds__(256) void round_copy_k(
    const float4* __restrict__ in, float4* __restrict__ out)
{
    const int i = blockIdx.x * 256 + threadIdx.x;
    float4 v = in[i];
    v.x = round_tf32(v.x); v.y = round_tf32(v.y);
    v.z = round_tf32(v.z); v.w = round_tf32(v.w);
    out[i] = v;
}

// ------------- pass A: per-chunk M = K^T diag(lamk) V  [64x64] --------------
__global__ __launch_bounds__(256) void chunk_kv_k(
    const float* __restrict__ Kg, const float* __restrict__ Vg,
    float* __restrict__ Mo)
{
    __shared__ float Ks[64][68];
    __shared__ float Vs[64][68];
    __shared__ float dpw[132];

    const int c = blockIdx.x, bh = blockIdx.y;
    const int b = bh >> 4, h = bh & 15;
    const int tid = threadIdx.x;
    const float s = head_slope(h);
    if (tid < 129) dpw[tid] = expf(-s * (float)tid);
    __syncthreads();

    const int tx = tid & 15, ty = tid >> 4;
    float acc[4][4];
#pragma unroll
    for (int i = 0; i < 4; i++)
#pragma unroll
        for (int j = 0; j < 4; j++) acc[i][j] = 0.f;

    const size_t rowbase = (size_t)b * 8192 + (size_t)c * 128;
    const int colbase = h * 64;

    for (int half = 0; half < 2; ++half) {
        if (half) __syncthreads();
        const int r = tid >> 2;
        const int f0 = tid & 3;
        const int jg = (half << 6) + r;
        const float lk = dpw[127 - jg];
        const size_t gr = (rowbase + jg) * 1024 + colbase;
#pragma unroll
        for (int it = 0; it < 4; ++it) {
            const int f = f0 + (it << 2);
            float4 k4 = *(const float4*)(Kg + gr + (f << 2));
            float4 v4 = *(const float4*)(Vg + gr + (f << 2));
            k4.x *= lk; k4.y *= lk; k4.z *= lk; k4.w *= lk;
            *(float4*)&Ks[r][f << 2] = k4;
            *(float4*)&Vs[r][f << 2] = v4;
        }
        __syncthreads();
        for (int j = 0; j < 64; ++j) {
            float4 ka = *(float4*)&Ks[j][ty << 2];
            float4 vb = *(float4*)&Vs[j][tx << 2];
            float kr[4] = {ka.x, ka.y, ka.z, ka.w};
            float vr[4] = {vb.x, vb.y, vb.z, vb.w};
#pragma unroll
            for (int i = 0; i < 4; i++)
#pragma unroll
                for (int q = 0; q < 4; q++)
                    acc[i][q] = fmaf(kr[i], vr[q], acc[i][q]);
        }
    }

    float* out = Mo + ((size_t)bh * NCH + c) * 4096;
#pragma unroll
    for (int r = 0; r < 4; r++) {
        float4 o = make_float4(acc[r][0], acc[r][1], acc[r][2], acc[r][3]);
        *(float4*)(out + ((ty << 2) + r) * 64 + (tx << 2)) = o;
    }
}

// ------------- pass B: decayed prefix scan of M over chunks -----------------
__global__ __launch_bounds__(256) void kv_scan_k(
    const float* __restrict__ Mi, float* __restrict__ KVo)
{
    const int bh = blockIdx.y;
    const int elem = blockIdx.x * 256 + threadIdx.x;   // 0..4095
    const int h = bh & 15;
    const float s = head_slope(h);
    const float lamc = expf(-s * 128.f);

    float acc = 0.f;
    const size_t base = (size_t)bh * NCH * 4096 + elem;
    for (int c = 0; c < NCH; ++c) {
        const size_t idx = base + (size_t)c * 4096;
        KVo[idx] = acc;
        acc = fmaf(lamc, acc, Mi[idx]);
    }
}

// ------------- pass C (mma): O = (mask o QK^T) V + lamq o (Q @ KVin) --------
// smem float layout: dpw[132] | Qs[128*68] | Ks/Vs[128*68] | KVs[64*68] | Ss[128*132]
#define AT_QS  132
#define AT_KS  (AT_QS + 128 * 68)
#define AT_KV  (AT_KS + 128 * 68)
#define AT_SS  (AT_KV + 64 * 68)
#define AT_TOT (AT_SS + 128 * 132)

__global__ __launch_bounds__(256) void attn_mma_k(
    const float* __restrict__ Qg, const float* __restrict__ Kg,
    const float* __restrict__ Vg, const float* __restrict__ KVi,
    float* __restrict__ Og)
{
    extern __shared__ float sm[];
    float* dpw = sm;
    float* Qs = sm + AT_QS;
    float* Ks = sm + AT_KS;        // later reused for V
    float* KVs = sm + AT_KV;
    float* Ss = sm + AT_SS;

    const int c = blockIdx.x, bh = blockIdx.y;
    const int b = bh >> 4, h = bh & 15;
    const int tid = threadIdx.x;
    const int lane = tid & 31, wid = tid >> 5;
    const int gid = lane >> 2, tg = lane & 3;
    const float s = head_slope(h);
    if (tid < 129) dpw[tid] = expf(-s * (float)tid);

    const size_t rowbase = (size_t)b * 8192 + (size_t)c * 128;
    const int colbase = h * 64;

    // load Q,K rows (already tf32-rounded) and KV (round here)
    {
        const int r = tid >> 1;
        const int fb = (tid & 1) * 8;
        const size_t gr = (rowbase + r) * 1024 + colbase;
#pragma unroll
        for (int it = 0; it < 8; ++it) {
            const int f4 = (fb + it) << 2;
            *(float4*)&Qs[r * 68 + f4] = *(const float4*)(Qg + gr + f4);
            *(float4*)&Ks[r * 68 + f4] = *(const float4*)(Kg + gr + f4);
        }
        const float* kvsrc = KVi + ((size_t)bh * NCH + c) * 4096;
#pragma unroll
        for (int it = 0; it < 4; ++it) {
            const int idx = tid + (it << 8);
            float4 v4 = *(const float4*)(kvsrc + (idx << 2));
            v4.x = round_tf32(v4.x); v4.y = round_tf32(v4.y);
            v4.z = round_tf32(v4.z); v4.w = round_tf32(v4.w);
            *(float4*)&KVs[(idx >> 4) * 68 + ((idx & 15) << 2)] = v4;
        }
    }
    __syncthreads();

    // ---- phase 1: S = Q @ K^T  (warp tile 64x32) ----
    const int wmS = (wid >> 2) * 64, wnS = (wid & 3) * 32;
    float sc[4][4][4];
#pragma unroll
    for (int i = 0; i < 4; i++)
#pragma unroll
        for (int j = 0; j < 4; j++)
#pragma unroll
            for (int q = 0; q < 4; q++) sc[i][j][q] = 0.f;

#pragma unroll
    for (int ks = 0; ks < 8; ++ks) {
        const int k0 = ks * 8;
        uint32_t af[4][4], bf[4][2];
#pragma unroll
        for (int mt = 0; mt < 4; mt++) {
            const int m = wmS + mt * 16 + gid;
            af[mt][0] = __float_as_uint(Qs[m * 68 + k0 + tg]);
            af[mt][1] = __float_as_uint(Qs[(m + 8) * 68 + k0 + tg]);
            af[mt][2] = __float_as_uint(Qs[m * 68 + k0 + tg + 4]);
            af[mt][3] = __float_as_uint(Qs[(m + 8) * 68 + k0 + tg + 4]);
        }
#pragma unroll
        for (int nt = 0; nt < 4; nt++) {
            const int n = wnS + nt * 8 + gid;
            bf[nt][0] = __float_as_uint(Ks[n * 68 + k0 + tg]);
            bf[nt][1] = __float_as_uint(Ks[n * 68 + k0 + tg + 4]);
        }
#pragma unroll
        for (int mt = 0; mt < 4; mt++)
#pragma unroll
            for (int nt = 0; nt < 4; nt++)
                MMA_TF32(sc[mt][nt], af[mt][0], af[mt][1], af[mt][2], af[mt][3],
                         bf[nt][0], bf[nt][1]);
    }

    // mask + decay + round, write S to smem
#pragma unroll
    for (int mt = 0; mt < 4; mt++) {
#pragma unroll
        for (int nt = 0; nt < 4; nt++) {
            const int i0 = wmS + mt * 16 + gid;
            const int j0 = wnS + nt * 8 + 2 * tg;
            const int d00 = i0 - j0;
            float* r0 = Ss + i0 * 132 + j0;
            float* r1 = Ss + (i0 + 8) * 132 + j0;
            r0[0] = (d00 >= 0) ? round_tf32(sc[mt][nt][0] * dpw[d00]) : 0.f;
            r0[1] = (d00 >= 1) ? round_tf32(sc[mt][nt][1] * dpw[d00 - 1]) : 0.f;
            r1[0] = (d00 >= -8) ? round_tf32(sc[mt][nt][2] * dpw[d00 + 8]) : 0.f;
            r1[1] = (d00 >= -7) ? round_tf32(sc[mt][nt][3] * dpw[d00 + 7]) : 0.f;
        }
    }

    // ---- phase 3: oc = Q @ KV  (warp tile 64x16) ----
    const int wmO = wmS, wnO = (wid & 3) * 16;
    float oc[4][2][4];
#pragma unroll
    for (int i = 0; i < 4; i++)
#pragma unroll
        for (int j = 0; j < 2; j++)
#pragma unroll
            for (int q = 0; q < 4; q++) oc[i][j][q] = 0.f;

#pragma unroll
    for (int ks = 0; ks < 8; ++ks) {
        const int k0 = ks * 8;
        uint32_t af[4][4], bf[2][2];
#pragma unroll
        for (int mt = 0; mt < 4; mt++) {
            const int m = wmO + mt * 16 + gid;
            af[mt][0] = __float_as_uint(Qs[m * 68 + k0 + tg]);
            af[mt][1] = __float_as_uint(Qs[(m + 8) * 68 + k0 + tg]);
            af[mt][2] = __float_as_uint(Qs[m * 68 + k0 + tg + 4]);
            af[mt][3] = __float_as_uint(Qs[(m + 8) * 68 + k0 + tg + 4]);
        }
#pragma unroll
        for (int nt = 0; nt < 2; nt++) {
            const int n = wnO + nt * 8 + gid;
            bf[nt][0] = __float_as_uint(KVs[(k0 + tg) * 68 + n]);
            bf[nt][1] = __float_as_uint(KVs[(k0 + tg + 4) * 68 + n]);
        }
#pragma unroll
        for (int mt = 0; mt < 4; mt++)
#pragma unroll
            for (int nt = 0; nt < 2; nt++)
                MMA_TF32(oc[mt][nt], af[mt][0], af[mt][1], af[mt][2], af[mt][3],
                         bf[nt][0], bf[nt][1]);
    }

    // scale by lamq[i] = dpw[i+1]
#pragma unroll
    for (int mt = 0; mt < 4; mt++) {
        const int i0 = wmO + mt * 16 + gid;
        const float l0 = dpw[i0 + 1], l1 = dpw[i0 + 9];
#pragma unroll
        for (int nt = 0; nt < 2; nt++) {
            oc[mt][nt][0] *= l0; oc[mt][nt][1] *= l0;
            oc[mt][nt][2] *= l1; oc[mt][nt][3] *= l1;
        }
    }

    __syncthreads();      // all S written, all K reads done

    // load V into Ks region (already tf32-rounded)
    {
        const int r = tid >> 1;
        const int fb = (tid & 1) * 8;
        const size_t gr = (rowbase + r) * 1024 + colbase;
#pragma unroll
        for (int it = 0; it < 8; ++it) {
            const int f4 = (fb + it) << 2;
            *(float4*)&Ks[r * 68 + f4] = *(const float4*)(Vg + gr + f4);
        }
    }
    __syncthreads();

    // ---- phase 2: oc += S @ V ----
#pragma unroll
    for (int ks = 0; ks < 16; ++ks) {
        const int k0 = ks * 8;
        uint32_t af[4][4], bf[2][2];
#pragma unroll
        for (int mt = 0; mt < 4; mt++) {
            const int m = wmO + mt * 16 + gid;
            af[mt][0] = __float_as_uint(Ss[m * 132 + k0 + tg]);
            af[mt][1] = __float_as_uint(Ss[(m + 8) * 132 + k0 + tg]);
            af[mt][2] = __float_as_uint(Ss[m * 132 + k0 + tg + 4]);
            af[mt][3] = __float_as_uint(Ss[(m + 8) * 132 + k0 + tg + 4]);
        }
#pragma unroll
        for (int nt = 0; nt < 2; nt++) {
            const int n = wnO + nt * 8 + gid;
            bf[nt][0] = __float_as_uint(Ks[(k0 + tg) * 68 + n]);
            bf[nt][1] = __float_as_uint(Ks[(k0 + tg + 4) * 68 + n]);
        }
#pragma unroll
        for (int mt = 0; mt < 4; mt++)
#pragma unroll
            for (int nt = 0; nt < 2; nt++)
                MMA_TF32(oc[mt][nt], af[mt][0], af[mt][1], af[mt][2], af[mt][3],
                         bf[nt][0], bf[nt][1]);
    }

    // write O
#pragma unroll
    for (int mt = 0; mt < 4; mt++) {
#pragma unroll
        for (int nt = 0; nt < 2; nt++) {
            const int i0 = wmO + mt * 16 + gid;
            const int e0 = wnO + nt * 8 + 2 * tg;
            float2 lo = make_float2(oc[mt][nt][0], oc[mt][nt][1]);
            float2 hi = make_float2(oc[mt][nt][2], oc[mt][nt][3]);
            *(float2*)(Og + (rowbase + i0) * 1024 + colbase + e0) = lo;
            *(float2*)(Og + (rowbase + i0 + 8) * 1024 + colbase + e0) = hi;
        }
    }
}

// ------------- LayerNorm * gate (rounded for the final GEMM) ---------------
__global__ __launch_bounds__(256) void ln_gate_k(
    const float* __restrict__ O, const float* __restrict__ G,
    const float* __restrict__ gamma, const float* __restrict__ beta,
    float* __restrict__ OG)
{
    __shared__ float red[2][8];
    const int row = blockIdx.x, tid = threadIdx.x;
    const size_t base = (size_t)row * 1024 + (tid << 2);
    float4 v = *(const float4*)(O + base);
    float sum = v.x + v.y + v.z + v.w;
    float sq = v.x * v.x + v.y * v.y + v.z * v.z + v.w * v.w;
#pragma unroll
    for (int o = 16; o > 0; o >>= 1) {
        sum += __shfl_xor_sync(0xffffffff, sum, o);
        sq += __shfl_xor_sync(0xffffffff, sq, o);
    }
    if ((tid & 31) == 0) { red[0][tid >> 5] = sum; red[1][tid >> 5] = sq; }
    __syncthreads();
    float ts = 0.f, tq = 0.f;
#pragma unroll
    for (int w = 0; w < 8; w++) { ts += red[0][w]; tq += red[1][w]; }
    const float mu = ts * (1.f / 1024.f);
    const float var = tq * (1.f / 1024.f) - mu * mu;
    const float rstd = rsqrtf(var + 1e-5f);

    float4 g4 = *(const float4*)(gamma + (tid << 2));
    float4 b4 = *(const float4*)(beta + (tid << 2));
    float4 gt = *(const float4*)(G + base);
    float4 o;
    o.x = round_tf32(((v.x - mu) * rstd * g4.x + b4.x) * gt.x);
    o.y = round_tf32(((v.y - mu) * rstd * g4.y + b4.y) * gt.y);
    o.z = round_tf32(((v.z - mu) * rstd * g4.z + b4.z) * gt.z);
    o.w = round_tf32(((v.w - mu) * rstd * g4.w + b4.w) * gt.w);
    *(float4*)(OG + base) = o;
}

// ---------------------------------------------------------------------------
extern "C" void kernel_launch(void* const* d_in, const int* in_sizes, int n_in,
                              void* d_out, int out_size)
{
    const float* x     = (const float*)d_in[0];
    const float* Wq    = (const float*)d_in[1];
    const float* Wk    = (const float*)d_in[2];
    const float* Wv    = (const float*)d_in[3];
    const float* Wo    = (const float*)d_in[4];
    const float* gamma = (const float*)d_in[5];
    const float* beta  = (const float*)d_in[6];
    const float* Wg1   = (const float*)d_in[7];
    const float* Wg2   = (const float*)d_in[8];
    float* out = (float*)d_out;

    void *pQ, *pK, *pV, *pO, *pGATE, *pG1, *pM, *pKV, *pXR;
    void *pWq, *pWk, *pWv, *pWo, *pWg1, *pWg2;
    cudaGetSymbolAddress(&pQ, gQ);
    cudaGetSymbolAddress(&pK, gK);
    cudaGetSymbolAddress(&pV, gV);
    cudaGetSymbolAddress(&pO, gO);
    cudaGetSymbolAddress(&pGATE, gGATE);
    cudaGetSymbolAddress(&pG1, gG1);
    cudaGetSymbolAddress(&pM, gM);
    cudaGetSymbolAddress(&pKV, gKV);
    cudaGetSymbolAddress(&pXR, gXR);
    cudaGetSymbolAddress(&pWq, gWqR);
    cudaGetSymbolAddress(&pWk, gWkR);
    cudaGetSymbolAddress(&pWv, gWvR);
    cudaGetSymbolAddress(&pWo, gWoR);
    cudaGetSymbolAddress(&pWg1, gWg1R);
    cudaGetSymbolAddress(&pWg2, gWg2R);
    float* Q = (float*)pQ;   float* Kb = (float*)pK;   float* Vb = (float*)pV;
    float* Ob = (float*)pO;  float* GATE = (float*)pGATE; float* G1 = (float*)pG1;
    float* Mb = (float*)pM;  float* KVb = (float*)pKV; float* XR = (float*)pXR;
    float* WqR = (float*)pWq; float* WkR = (float*)pWk; float* WvR = (float*)pWv;
    float* WoR = (float*)pWo; float* Wg1R = (float*)pWg1; float* Wg2R = (float*)pWg2;

    const int smem128 = 3 * (128 * ASTR + 32 * 136) * 4;   // 107520
    const int smem64  = 3 * (128 * ASTR + 32 * 72) * 4;    //  82944
    const int smemAttn = AT_TOT * 4;                       // ~155 KB
    cudaFuncSetAttribute(tgemm2_k<1, 128, true>,
                         cudaFuncAttributeMaxDynamicSharedMemorySize, smem128);
    cudaFuncSetAttribute(tgemm2_k<0, 128, false>,
                         cudaFuncAttributeMaxDynamicSharedMemorySize, smem128);
    cudaFuncSetAttribute(tgemm2_k<2, 128, false>,
                         cudaFuncAttributeMaxDynamicSharedMemorySize, smem128);
    cudaFuncSetAttribute(tgemm2_k<0, 64, true>,
                         cudaFuncAttributeMaxDynamicSharedMemorySize, smem64);
    cudaFuncSetAttribute(attn_mma_k,
                         cudaFuncAttributeMaxDynamicSharedMemorySize, smemAttn);

    // ---- prep: round x + weights to tf32 ----
    round_copy_k<<<MDIM * EDIM / 1024, 256>>>((const float4*)x, (float4*)XR);
    round_copy_k<<<EDIM * EDIM / 1024, 256>>>((const float4*)Wq, (float4*)WqR);
    round_copy_k<<<EDIM * EDIM / 1024, 256>>>((const float4*)Wk, (float4*)WkR);
    round_copy_k<<<EDIM * EDIM / 1024, 256>>>((const float4*)Wv, (float4*)WvR);
    round_copy_k<<<EDIM * EDIM / 1024, 256>>>((const float4*)Wo, (float4*)WoR);
    round_copy_k<<<EDIM * DH / 1024, 256>>>((const float4*)Wg1, (float4*)Wg1R);
    round_copy_k<<<EDIM * DH / 1024, 256>>>((const float4*)Wg2, (float4*)Wg2R);

    dim3 tB(256);
    dim3 gBig(EDIM / 128, MDIM / 128);     // (8, 128)

    // projections (tf32 mma, silu epilogue, outputs rounded for attention mma)
    tgemm2_k<1, 128, true><<<gBig, tB, smem128>>>(XR, WqR, Q, MDIM, EDIM, EDIM);
    tgemm2_k<1, 128, true><<<gBig, tB, smem128>>>(XR, WkR, Kb, MDIM, EDIM, EDIM);
    tgemm2_k<1, 128, true><<<gBig, tB, smem128>>>(XR, WvR, Vb, MDIM, EDIM, EDIM);

    // gate path
    tgemm2_k<0, 64, true><<<dim3(1, MDIM / 128), tB, smem64>>>(XR, Wg1R, G1, MDIM, DH, EDIM);
    tgemm2_k<2, 128, false><<<gBig, tB, smem128>>>(G1, Wg2R, GATE, MDIM, EDIM, DH);

    // attention
    chunk_kv_k<<<dim3(NCH, BHN), 256>>>(Kb, Vb, Mb);
    kv_scan_k<<<dim3(16, BHN), 256>>>(Mb, KVb);
    attn_mma_k<<<dim3(NCH, BHN), 256, smemAttn>>>(Q, Kb, Vb, KVb, Ob);

    // layernorm * gate (rounded), final projection
    ln_gate_k<<<MDIM, 256>>>(Ob, GATE, gamma, beta, Ob);
    tgemm2_k<0, 128, false><<<gBig, tB, smem128>>>(Ob, WoR, out, MDIM, EDIM, EDIM);
}

// round 9
// speedup vs baseline: 3.0929x; 1.1240x over previous
#include <cuda_runtime.h>
#include <math.h>
#include <stdint.h>

// Problem constants
#define MDIM 16384          // B*N = 2*8192 rows
#define EDIM 1024           // embed
#define DH   64             // head dim
#define NCH  64             // chunks per sequence (8192/128)
#define BHN  32             // B*H

// ---------------- scratch (device globals) ----------------------------------
__device__ float gQ[MDIM * EDIM];
__device__ float gK[MDIM * EDIM];
__device__ float gV[MDIM * EDIM];
__device__ float gO[MDIM * EDIM];
__device__ float gGATE[MDIM * EDIM];
__device__ float gG1[MDIM * DH];
__device__ float gM[BHN * NCH * DH * DH];
__device__ float gKV[BHN * NCH * DH * DH];
__device__ float gXR[MDIM * EDIM];
__device__ float gWqT[EDIM * EDIM];
__device__ float gWkT[EDIM * EDIM];
__device__ float gWvT[EDIM * EDIM];
__device__ float gWoT[EDIM * EDIM];
__device__ float gWg1T[DH * EDIM];
__device__ float gWg2T[EDIM * DH];

__device__ __forceinline__ float head_slope(int h) {
    return exp2f(-0.5f * (float)(h + 1)) * 1.00001f;
}

template <int EPI>
__device__ __forceinline__ float epilogue(float v) {
    if (EPI == 1) return v / (1.f + expf(-v));      // silu
    if (EPI == 2) return 1.f / (1.f + expf(-v));    // sigmoid
    return v;
}

__device__ __forceinline__ uint32_t cvt_tf32(float x) {
    uint32_t r;
    asm("cvt.rna.tf32.f32 %0, %1;" : "=r"(r) : "f"(x));
    return r;
}
__device__ __forceinline__ float round_tf32(float x) {
    return __uint_as_float(cvt_tf32(x));
}

#define MMA_TF32(acc, a0, a1, a2, a3, b0, b1) \
    asm volatile( \
        "mma.sync.aligned.m16n8k8.row.col.f32.tf32.tf32.f32 " \
        "{%0,%1,%2,%3}, {%4,%5,%6,%7}, {%8,%9}, {%0,%1,%2,%3};\n" \
        : "+f"((acc)[0]), "+f"((acc)[1]), "+f"((acc)[2]), "+f"((acc)[3]) \
        : "r"(a0), "r"(a1), "r"(a2), "r"(a3), "r"(b0), "r"(b1))

// ldmatrix on 16B rows: one 8x4-b32 matrix per .m8n8.b16 matrix.
// x4 -> A m16k8 tf32 fragment; x2 -> B n8k8 tf32 fragment ([n][k] smem layout).
#define LDSM_X4(r, addr) \
    asm volatile("ldmatrix.sync.aligned.m8n8.x4.shared.b16 {%0,%1,%2,%3}, [%4];" \
        : "=r"((r)[0]), "=r"((r)[1]), "=r"((r)[2]), "=r"((r)[3]) : "r"(addr))
#define LDSM_X2(r, addr) \
    asm volatile("ldmatrix.sync.aligned.m8n8.x2.shared.b16 {%0,%1}, [%2];" \
        : "=r"((r)[0]), "=r"((r)[1]) : "r"(addr))

__device__ __forceinline__ void cpa_wait(int keep) {
    if (keep <= 0)      asm volatile("cp.async.wait_group 0;" ::);
    else                asm volatile("cp.async.wait_group 1;" ::);
}

// =================== TF32 mma.sync GEMM (ldmatrix fragments) ================
// C = epi(A @ Bt^T). A[M,K], Bt[N,K] row-major, both tf32-rounded already.
// 128 x BN_ x 32 tile, 256 thr (8 warps 2x4), warp tile 64 x (BN_/4),
// 3-stage cp.async, 1 sync/iter, ldmatrix fragment loads.
#define ASTR 36
template <int EPI, int BN_, bool RND>
__global__ __launch_bounds__(256, 2) void tgemm3_k(
    const float* __restrict__ A, const float* __restrict__ Bt,
    float* __restrict__ C, int M, int N, int K)
{
    constexpr int SA_F = 128 * ASTR;
    constexpr int SB_F = BN_ * ASTR;
    constexpr int STAGE_F = SA_F + SB_F;
    constexpr int BITER = BN_ / 32;
    constexpr int NT = BN_ / 32;

    extern __shared__ float sm[];
    const int tid = threadIdx.x;
    const int lane = tid & 31, wid = tid >> 5;
    const int gid = lane >> 2, tg = lane & 3;
    const int wm = (wid >> 2) * 64;
    const int wn = (wid & 3) * (BN_ / 4);
    const int bm = blockIdx.y << 7;
    const int bn = blockIdx.x * BN_;
    const uint32_t smu = (uint32_t)__cvta_generic_to_shared(sm);
    const int KT = K >> 5;

    // ldmatrix per-lane offsets
    const int arow = lane & 15;
    const int acol = (lane & 16) >> 2;     // 0 or 4
    const int brow = lane & 7;
    const int bcol = (lane & 8) >> 1;      // 0 or 4

    auto fill = [&](int kt) {
        const uint32_t sa = smu + (uint32_t)((kt % 3) * STAGE_F) * 4u;
        const uint32_t sb = sa + (uint32_t)SA_F * 4u;
#pragma unroll
        for (int i = 0; i < 4; i++) {
            const int idx = tid + (i << 8);
            const int row = idx >> 3, col = (idx & 7) << 2;
            const float* src = A + (size_t)(bm + row) * K + (kt << 5) + col;
            asm volatile("cp.async.cg.shared.global [%0], [%1], 16;"
                         :: "r"(sa + (uint32_t)(row * ASTR + col) * 4u), "l"(src));
        }
#pragma unroll
        for (int i = 0; i < BITER; i++) {
            const int idx = tid + (i << 8);
            const int row = idx >> 3, col = (idx & 7) << 2;
            const float* src = Bt + (size_t)(bn + row) * K + (kt << 5) + col;
            asm volatile("cp.async.cg.shared.global [%0], [%1], 16;"
                         :: "r"(sb + (uint32_t)(row * ASTR + col) * 4u), "l"(src));
        }
        asm volatile("cp.async.commit_group;");
    };

    float acc[4][NT][4];
#pragma unroll
    for (int i = 0; i < 4; i++)
#pragma unroll
        for (int j = 0; j < NT; j++)
#pragma unroll
            for (int q = 0; q < 4; q++) acc[i][j][q] = 0.f;

    fill(0);
    if (KT > 1) fill(1);

    for (int kt = 0; kt < KT; ++kt) {
        cpa_wait((kt + 1 < KT) ? 1 : 0);
        __syncthreads();
        if (kt + 2 < KT) fill(kt + 2);

        const uint32_t sa = smu + (uint32_t)((kt % 3) * STAGE_F) * 4u;
        const uint32_t sb = sa + (uint32_t)SA_F * 4u;
#pragma unroll
        for (int ks = 0; ks < 4; ++ks) {
            const int k0 = ks * 8;
            uint32_t af[4][4], bf[NT][2];
#pragma unroll
            for (int mt = 0; mt < 4; mt++)
                LDSM_X4(af[mt], sa + (uint32_t)(((wm + mt * 16 + arow) * ASTR) + k0 + acol) * 4u);
#pragma unroll
            for (int nt = 0; nt < NT; nt++)
                LDSM_X2(bf[nt], sb + (uint32_t)(((wn + nt * 8 + brow) * ASTR) + k0 + bcol) * 4u);
#pragma unroll
            for (int mt = 0; mt < 4; mt++)
#pragma unroll
                for (int nt = 0; nt < NT; nt++)
                    MMA_TF32(acc[mt][nt], af[mt][0], af[mt][1], af[mt][2], af[mt][3],
                             bf[nt][0], bf[nt][1]);
        }
    }

#pragma unroll
    for (int mt = 0; mt < 4; mt++) {
#pragma unroll
        for (int nt = 0; nt < NT; nt++) {
            const int r0 = bm + wm + mt * 16 + gid;
            const int c = bn + wn + nt * 8 + 2 * tg;
            float2 lo, hi;
            lo.x = epilogue<EPI>(acc[mt][nt][0]);
            lo.y = epilogue<EPI>(acc[mt][nt][1]);
            hi.x = epilogue<EPI>(acc[mt][nt][2]);
            hi.y = epilogue<EPI>(acc[mt][nt][3]);
            if (RND) {
                lo.x = round_tf32(lo.x); lo.y = round_tf32(lo.y);
                hi.x = round_tf32(hi.x); hi.y = round_tf32(hi.y);
            }
            *(float2*)(C + (size_t)r0 * N + c) = lo;
            *(float2*)(C + (size_t)(r0 + 8) * N + c) = hi;
        }
    }
}

// ---------------- prep kernels ---------------------------------------------
__global__ __launch_bounds__(256) void round_copy_k(
    const float4* __restrict__ in, float4* __restrict__ out)
{
    const int i = blockIdx.x * 256 + threadIdx.x;
    float4 v = in[i];
    v.x = round_tf32(v.x); v.y = round_tf32(v.y);
    v.z = round_tf32(v.z); v.w = round_tf32(v.w);
    out[i] = v;
}

// D[c][r] = rna(S[r][c]); S is RxC row-major. grid (C/32, R/32), 256 thr.
__global__ __launch_bounds__(256) void transpose_round_k(
    const float* __restrict__ S, float* __restrict__ D, int R, int C)
{
    __shared__ float t[32][33];
    const int bc = blockIdx.x * 32, br = blockIdx.y * 32;
    const int tx = threadIdx.x & 31, ty = threadIdx.x >> 5;
#pragma unroll
    for (int i = 0; i < 32; i += 8)
        t[ty + i][tx] = S[(size_t)(br + ty + i) * C + bc + tx];
    __syncthreads();
#pragma unroll
    for (int i = 0; i < 32; i += 8)
        D[(size_t)(bc + ty + i) * R + br + tx] = round_tf32(t[tx][ty + i]);
}

// ------------- pass A (mma): per-chunk M = K^T diag(lamk) V  [64x64] --------
// smem: dpw[132] | KsT[64*132] (d-major) | VsT[64*132] (e-major)
#define CK_KST 132
#define CK_VST (CK_KST + 64 * 132)
#define CK_TOT (CK_VST + 64 * 132)

__global__ __launch_bounds__(256) void ckv_mma_k(
    const float* __restrict__ Kg, const float* __restrict__ Vg,
    float* __restrict__ Mo)
{
    extern __shared__ float sm[];
    float* dpw = sm;
    float* KsT = sm + CK_KST;
    float* VsT = sm + CK_VST;
    const uint32_t smb = (uint32_t)__cvta_generic_to_shared(sm);
    const uint32_t kB = smb + CK_KST * 4u;
    const uint32_t vB = smb + CK_VST * 4u;

    const int c = blockIdx.x, bh = blockIdx.y;
    const int b = bh >> 4, h = bh & 15;
    const int tid = threadIdx.x;
    const int lane = tid & 31, wid = tid >> 5;
    const int gid = lane >> 2, tg = lane & 3;
    const int arow = lane & 15, acol = (lane & 16) >> 2;
    const int brow = lane & 7, bcol = (lane & 8) >> 1;
    const float s = head_slope(h);
    if (tid < 129) dpw[tid] = expf(-s * (float)tid);
    __syncthreads();

    const size_t rowbase = (size_t)b * 8192 + (size_t)c * 128;
    const int colbase = h * 64;

    // load K (scaled by lamk, rounded) and V, transposed into smem
#pragma unroll
    for (int it = 0; it < 8; ++it) {
        const int idx = tid + (it << 8);        // f4 slots, 2048 total
        const int j = idx >> 4;                 // chunk row 0..127
        const int e4 = (idx & 15) << 2;         // feature 0..60
        const size_t g = (rowbase + j) * 1024 + colbase + e4;
        float4 k4 = *(const float4*)(Kg + g);
        float4 v4 = *(const float4*)(Vg + g);
        const float lk = dpw[127 - j];
        KsT[(e4 + 0) * 132 + j] = round_tf32(k4.x * lk);
        KsT[(e4 + 1) * 132 + j] = round_tf32(k4.y * lk);
        KsT[(e4 + 2) * 132 + j] = round_tf32(k4.z * lk);
        KsT[(e4 + 3) * 132 + j] = round_tf32(k4.w * lk);
        VsT[(e4 + 0) * 132 + j] = v4.x;
        VsT[(e4 + 1) * 132 + j] = v4.y;
        VsT[(e4 + 2) * 132 + j] = v4.z;
        VsT[(e4 + 3) * 132 + j] = v4.w;
    }
    __syncthreads();

    // warp tile 32x16 (mt<2, nt<2), k = j over 128
    const int wm = (wid >> 2) * 32;
    const int wn = (wid & 3) * 16;
    float acc[2][2][4];
#pragma unroll
    for (int i = 0; i < 2; i++)
#pragma unroll
        for (int j = 0; j < 2; j++)
#pragma unroll
            for (int q = 0; q < 4; q++) acc[i][j][q] = 0.f;

#pragma unroll
    for (int ks = 0; ks < 16; ++ks) {
        const int k0 = ks * 8;
        uint32_t af[2][4], bf[2][2];
#pragma unroll
        for (int mt = 0; mt < 2; mt++)
            LDSM_X4(af[mt], kB + (uint32_t)(((wm + mt * 16 + arow) * 132) + k0 + acol) * 4u);
#pragma unroll
        for (int nt = 0; nt < 2; nt++)
            LDSM_X2(bf[nt], vB + (uint32_t)(((wn + nt * 8 + brow) * 132) + k0 + bcol) * 4u);
#pragma unroll
        for (int mt = 0; mt < 2; mt++)
#pragma unroll
            for (int nt = 0; nt < 2; nt++)
                MMA_TF32(acc[mt][nt], af[mt][0], af[mt][1], af[mt][2], af[mt][3],
                         bf[nt][0], bf[nt][1]);
    }

    float* out = Mo + ((size_t)bh * NCH + c) * 4096;
#pragma unroll
    for (int mt = 0; mt < 2; mt++) {
#pragma unroll
        for (int nt = 0; nt < 2; nt++) {
            const int i0 = wm + mt * 16 + gid;
            const int j0 = wn + nt * 8 + 2 * tg;
            *(float2*)(out + i0 * 64 + j0) = make_float2(acc[mt][nt][0], acc[mt][nt][1]);
            *(float2*)(out + (i0 + 8) * 64 + j0) = make_float2(acc[mt][nt][2], acc[mt][nt][3]);
        }
    }
}

// ------------- pass B: decayed prefix scan of M over chunks -----------------
__global__ __launch_bounds__(256) void kv_scan_k(
    const float* __restrict__ Mi, float* __restrict__ KVo)
{
    const int bh = blockIdx.y;
    const int elem = blockIdx.x * 256 + threadIdx.x;   // 0..4095
    const int h = bh & 15;
    const float s = head_slope(h);
    const float lamc = expf(-s * 128.f);

    float acc = 0.f;
    const size_t base = (size_t)bh * NCH * 4096 + elem;
    for (int c = 0; c < NCH; ++c) {
        const size_t idx = base + (size_t)c * 4096;
        KVo[idx] = acc;
        acc = fmaf(lamc, acc, Mi[idx]);
    }
}

// ------------- pass C (mma): O = (mask o QK^T) V + lamq o (Q @ KVin) --------
// smem: dpw[132] | Qs[128*68] | Ks/Vs[128*68] | KVsT[64*68] (e-major) | Ss[128*132]
#define AT_QS  132
#define AT_KS  (AT_QS + 128 * 68)
#define AT_KV  (AT_KS + 128 * 68)
#define AT_SS  (AT_KV + 64 * 68)
#define AT_TOT (AT_SS + 128 * 132)

__global__ __launch_bounds__(256) void attn_mma_k(
    const float* __restrict__ Qg, const float* __restrict__ Kg,
    const float* __restrict__ Vg, const float* __restrict__ KVi,
    float* __restrict__ Og)
{
    extern __shared__ float sm[];
    float* dpw = sm;
    float* Qs = sm + AT_QS;
    float* Ks = sm + AT_KS;        // later reused for V
    float* KVs = sm + AT_KV;       // [e][d] (transposed)
    float* Ss = sm + AT_SS;
    const uint32_t smb = (uint32_t)__cvta_generic_to_shared(sm);
    const uint32_t qB = smb + AT_QS * 4u;
    const uint32_t kB = smb + AT_KS * 4u;
    const uint32_t kvB = smb + AT_KV * 4u;
    const uint32_t sB = smb + AT_SS * 4u;

    const int c = blockIdx.x, bh = blockIdx.y;
    const int b = bh >> 4, h = bh & 15;
    const int tid = threadIdx.x;
    const int lane = tid & 31, wid = tid >> 5;
    const int gid = lane >> 2, tg = lane & 3;
    const int arow = lane & 15, acol = (lane & 16) >> 2;
    const int brow = lane & 7, bcol = (lane & 8) >> 1;
    const float s = head_slope(h);
    if (tid < 129) dpw[tid] = expf(-s * (float)tid);

    const size_t rowbase = (size_t)b * 8192 + (size_t)c * 128;
    const int colbase = h * 64;

    // load Q,K rows (tf32-rounded) and KV (rounded, transposed to [e][d])
    {
        const int r = tid >> 1;
        const int fb = (tid & 1) * 8;
        const size_t gr = (rowbase + r) * 1024 + colbase;
#pragma unroll
        for (int it = 0; it < 8; ++it) {
            const int f4 = (fb + it) << 2;
            *(float4*)&Qs[r * 68 + f4] = *(const float4*)(Qg + gr + f4);
            *(float4*)&Ks[r * 68 + f4] = *(const float4*)(Kg + gr + f4);
        }
        const float* kvsrc = KVi + ((size_t)bh * NCH + c) * 4096;
#pragma unroll
        for (int it = 0; it < 4; ++it) {
            const int idx = tid + (it << 8);      // f4 slot: d = idx>>4, e4 = (idx&15)*4
            float4 v4 = *(const float4*)(kvsrc + (idx << 2));
            const int d = idx >> 4, e4 = (idx & 15) << 2;
            KVs[(e4 + 0) * 68 + d] = round_tf32(v4.x);
            KVs[(e4 + 1) * 68 + d] = round_tf32(v4.y);
            KVs[(e4 + 2) * 68 + d] = round_tf32(v4.z);
            KVs[(e4 + 3) * 68 + d] = round_tf32(v4.w);
        }
    }
    __syncthreads();

    // ---- merged phase 1+3: S = Q K^T (64x32 tile), oc = Q KV (64x16 tile) --
    const int wmS = (wid >> 2) * 64, wnS = (wid & 3) * 32;
    const int wnO = (wid & 3) * 16;
    float sc[4][4][4];
    float oc[4][2][4];
#pragma unroll
    for (int i = 0; i < 4; i++) {
#pragma unroll
        for (int j = 0; j < 4; j++)
#pragma unroll
            for (int q = 0; q < 4; q++) sc[i][j][q] = 0.f;
#pragma unroll
        for (int j = 0; j < 2; j++)
#pragma unroll
            for (int q = 0; q < 4; q++) oc[i][j][q] = 0.f;
    }

#pragma unroll
    for (int ks = 0; ks < 8; ++ks) {
        const int k0 = ks * 8;
        uint32_t af[4][4], bf[4][2], bk[2][2];
#pragma unroll
        for (int mt = 0; mt < 4; mt++)
            LDSM_X4(af[mt], qB + (uint32_t)(((wmS + mt * 16 + arow) * 68) + k0 + acol) * 4u);
#pragma unroll
        for (int nt = 0; nt < 4; nt++)
            LDSM_X2(bf[nt], kB + (uint32_t)(((wnS + nt * 8 + brow) * 68) + k0 + bcol) * 4u);
#pragma unroll
        for (int nt = 0; nt < 2; nt++)
            LDSM_X2(bk[nt], kvB + (uint32_t)(((wnO + nt * 8 + brow) * 68) + k0 + bcol) * 4u);
#pragma unroll
        for (int mt = 0; mt < 4; mt++) {
#pragma unroll
            for (int nt = 0; nt < 4; nt++)
                MMA_TF32(sc[mt][nt], af[mt][0], af[mt][1], af[mt][2], af[mt][3],
                         bf[nt][0], bf[nt][1]);
#pragma unroll
            for (int nt = 0; nt < 2; nt++)
                MMA_TF32(oc[mt][nt], af[mt][0], af[mt][1], af[mt][2], af[mt][3],
                         bk[nt][0], bk[nt][1]);
        }
    }

    // mask + decay + round, write S to smem
#pragma unroll
    for (int mt = 0; mt < 4; mt++) {
#pragma unroll
        for (int nt = 0; nt < 4; nt++) {
            const int i0 = wmS + mt * 16 + gid;
            const int j0 = wnS + nt * 8 + 2 * tg;
            const int d00 = i0 - j0;
            float* r0 = Ss + i0 * 132 + j0;
            float* r1 = Ss + (i0 + 8) * 132 + j0;
            r0[0] = (d00 >= 0) ? round_tf32(sc[mt][nt][0] * dpw[d00]) : 0.f;
            r0[1] = (d00 >= 1) ? round_tf32(sc[mt][nt][1] * dpw[d00 - 1]) : 0.f;
            r1[0] = (d00 >= -8) ? round_tf32(sc[mt][nt][2] * dpw[d00 + 8]) : 0.f;
            r1[1] = (d00 >= -7) ? round_tf32(sc[mt][nt][3] * dpw[d00 + 7]) : 0.f;
        }
    }

    // scale oc by lamq[i] = dpw[i+1]
#pragma unroll
    for (int mt = 0; mt < 4; mt++) {
        const int i0 = wmS + mt * 16 + gid;
        const float l0 = dpw[i0 + 1], l1 = dpw[i0 + 9];
#pragma unroll
        for (int nt = 0; nt < 2; nt++) {
            oc[mt][nt][0] *= l0; oc[mt][nt][1] *= l0;
            oc[mt][nt][2] *= l1; oc[mt][nt][3] *= l1;
        }
    }

    __syncthreads();      // all S written, all K/KV reads done

    // load V into Ks region (already tf32-rounded), layout [j][e]
    {
        const int r = tid >> 1;
        const int fb = (tid & 1) * 8;
        const size_t gr = (rowbase + r) * 1024 + colbase;
#pragma unroll
        for (int it = 0; it < 8; ++it) {
            const int f4 = (fb + it) << 2;
            *(float4*)&Ks[r * 68 + f4] = *(const float4*)(Vg + gr + f4);
        }
    }
    __syncthreads();

    // ---- phase 2: oc += S @ V  (A via ldmatrix from Ss; B scalar from Vs) --
#pragma unroll
    for (int ks = 0; ks < 16; ++ks) {
        const int k0 = ks * 8;
        uint32_t af[4][4], bf[2][2];
#pragma unroll
        for (int mt = 0; mt < 4; mt++)
            LDSM_X4(af[mt], sB + (uint32_t)(((wmS + mt * 16 + arow) * 132) + k0 + acol) * 4u);
#pragma unroll
        for (int nt = 0; nt < 2; nt++) {
            const int n = wnO + nt * 8 + gid;
            bf[nt][0] = __float_as_uint(Ks[(k0 + tg) * 68 + n]);
            bf[nt][1] = __float_as_uint(Ks[(k0 + tg + 4) * 68 + n]);
        }
#pragma unroll
        for (int mt = 0; mt < 4; mt++)
#pragma unroll
            for (int nt = 0; nt < 2; nt++)
                MMA_TF32(oc[mt][nt], af[mt][0], af[mt][1], af[mt][2], af[mt][3],
                         bf[nt][0], bf[nt][1]);
    }

    // write O
#pragma unroll
    for (int mt = 0; mt < 4; mt++) {
#pragma unroll
        for (int nt = 0; nt < 2; nt++) {
            const int i0 = wmS + mt * 16 + gid;
            const int e0 = wnO + nt * 8 + 2 * tg;
            *(float2*)(Og + (rowbase + i0) * 1024 + colbase + e0) =
                make_float2(oc[mt][nt][0], oc[mt][nt][1]);
            *(float2*)(Og + (rowbase + i0 + 8) * 1024 + colbase + e0) =
                make_float2(oc[mt][nt][2], oc[mt][nt][3]);
        }
    }
}

// ------------- LayerNorm * gate (rounded for the final GEMM) ---------------
__global__ __launch_bounds__(256) void ln_gate_k(
    const float* __restrict__ O, const float* __restrict__ G,
    const float* __restrict__ gamma, const float* __restrict__ beta,
    float* __restrict__ OG)
{
    __shared__ float red[2][8];
    const int row = blockIdx.x, tid = threadIdx.x;
    const size_t base = (size_t)row * 1024 + (tid << 2);
    float4 v = *(const float4*)(O + base);
    float sum = v.x + v.y + v.z + v.w;
    float sq = v.x * v.x + v.y * v.y + v.z * v.z + v.w * v.w;
#pragma unroll
    for (int o = 16; o > 0; o >>= 1) {
        sum += __shfl_xor_sync(0xffffffff, sum, o);
        sq += __shfl_xor_sync(0xffffffff, sq, o);
    }
    if ((tid & 31) == 0) { red[0][tid >> 5] = sum; red[1][tid >> 5] = sq; }
    __syncthreads();
    float ts = 0.f, tq = 0.f;
#pragma unroll
    for (int w = 0; w < 8; w++) { ts += red[0][w]; tq += red[1][w]; }
    const float mu = ts * (1.f / 1024.f);
    const float var = tq * (1.f / 1024.f) - mu * mu;
    const float rstd = rsqrtf(var + 1e-5f);

    float4 g4 = *(const float4*)(gamma + (tid << 2));
    float4 b4 = *(const float4*)(beta + (tid << 2));
    float4 gt = *(const float4*)(G + base);
    float4 o;
    o.x = round_tf32(((v.x - mu) * rstd * g4.x + b4.x) * gt.x);
    o.y = round_tf32(((v.y - mu) * rstd * g4.y + b4.y) * gt.y);
    o.z = round_tf32(((v.z - mu) * rstd * g4.z + b4.z) * gt.z);
    o.w = round_tf32(((v.w - mu) * rstd * g4.w + b4.w) * gt.w);
    *(float4*)(OG + base) = o;
}

// ---------------------------------------------------------------------------
extern "C" void kernel_launch(void* const* d_in, const int* in_sizes, int n_in,
                              void* d_out, int out_size)
{
    const float* x     = (const float*)d_in[0];
    const float* Wq    = (const float*)d_in[1];
    const float* Wk    = (const float*)d_in[2];
    const float* Wv    = (const float*)d_in[3];
    const float* Wo    = (const float*)d_in[4];
    const float* gamma = (const float*)d_in[5];
    const float* beta  = (const float*)d_in[6];
    const float* Wg1   = (const float*)d_in[7];
    const float* Wg2   = (const float*)d_in[8];
    float* out = (float*)d_out;

    void *pQ, *pK, *pV, *pO, *pGATE, *pG1, *pM, *pKV, *pXR;
    void *pWq, *pWk, *pWv, *pWo, *pWg1, *pWg2;
    cudaGetSymbolAddress(&pQ, gQ);
    cudaGetSymbolAddress(&pK, gK);
    cudaGetSymbolAddress(&pV, gV);
    cudaGetSymbolAddress(&pO, gO);
    cudaGetSymbolAddress(&pGATE, gGATE);
    cudaGetSymbolAddress(&pG1, gG1);
    cudaGetSymbolAddress(&pM, gM);
    cudaGetSymbolAddress(&pKV, gKV);
    cudaGetSymbolAddress(&pXR, gXR);
    cudaGetSymbolAddress(&pWq, gWqT);
    cudaGetSymbolAddress(&pWk, gWkT);
    cudaGetSymbolAddress(&pWv, gWvT);
    cudaGetSymbolAddress(&pWo, gWoT);
    cudaGetSymbolAddress(&pWg1, gWg1T);
    cudaGetSymbolAddress(&pWg2, gWg2T);
    float* Q = (float*)pQ;   float* Kb = (float*)pK;   float* Vb = (float*)pV;
    float* Ob = (float*)pO;  float* GATE = (float*)pGATE; float* G1 = (float*)pG1;
    float* Mb = (float*)pM;  float* KVb = (float*)pKV; float* XR = (float*)pXR;
    float* WqT = (float*)pWq; float* WkT = (float*)pWk; float* WvT = (float*)pWv;
    float* WoT = (float*)pWo; float* Wg1T = (float*)pWg1; float* Wg2T = (float*)pWg2;

    const int smem128 = 3 * (128 + 128) * ASTR * 4;    // 110592
    const int smem64  = 3 * (128 + 64) * ASTR * 4;     //  82944
    const int smemAttn = AT_TOT * 4;                   // ~155 KB
    const int smemCkv = CK_TOT * 4;                    // ~68 KB
    cudaFuncSetAttribute(tgemm3_k<1, 128, true>,
                         cudaFuncAttributeMaxDynamicSharedMemorySize, smem128);
    cudaFuncSetAttribute(tgemm3_k<0, 128, false>,
                         cudaFuncAttributeMaxDynamicSharedMemorySize, smem128);
    cudaFuncSetAttribute(tgemm3_k<2, 128, false>,
                         cudaFuncAttributeMaxDynamicSharedMemorySize, smem128);
    cudaFuncSetAttribute(tgemm3_k<0, 64, true>,
                         cudaFuncAttributeMaxDynamicSharedMemorySize, smem64);
    cudaFuncSetAttribute(attn_mma_k,
                         cudaFuncAttributeMaxDynamicSharedMemorySize, smemAttn);
    cudaFuncSetAttribute(ckv_mma_k,
                         cudaFuncAttributeMaxDynamicSharedMemorySize, smemCkv);

    // ---- prep: round x; transpose+round weights to [N][K] ----
    round_copy_k<<<MDIM * EDIM / 1024, 256>>>((const float4*)x, (float4*)XR);
    transpose_round_k<<<dim3(32, 32), 256>>>(Wq, WqT, EDIM, EDIM);
    transpose_round_k<<<dim3(32, 32), 256>>>(Wk, WkT, EDIM, EDIM);
    transpose_round_k<<<dim3(32, 32), 256>>>(Wv, WvT, EDIM, EDIM);
    transpose_round_k<<<dim3(32, 32), 256>>>(Wo, WoT, EDIM, EDIM);
    transpose_round_k<<<dim3(2, 32), 256>>>(Wg1, Wg1T, EDIM, DH);   // -> [64][1024]
    transpose_round_k<<<dim3(32, 2), 256>>>(Wg2, Wg2T, DH, EDIM);   // -> [1024][64]

    dim3 tB(256);
    dim3 gBig(EDIM / 128, MDIM / 128);     // (8, 128)

    // projections (tf32 mma + ldmatrix, silu epilogue, outputs rounded)
    tgemm3_k<1, 128, true><<<gBig, tB, smem128>>>(XR, WqT, Q, MDIM, EDIM, EDIM);
    tgemm3_k<1, 128, true><<<gBig, tB, smem128>>>(XR, WkT, Kb, MDIM, EDIM, EDIM);
    tgemm3_k<1, 128, true><<<gBig, tB, smem128>>>(XR, WvT, Vb, MDIM, EDIM, EDIM);

    // gate path
    tgemm3_k<0, 64, true><<<dim3(1, MDIM / 128), tB, smem64>>>(XR, Wg1T, G1, MDIM, DH, EDIM);
    tgemm3_k<2, 128, false><<<gBig, tB, smem128>>>(G1, Wg2T, GATE, MDIM, EDIM, DH);

    // attention
    ckv_mma_k<<<dim3(NCH, BHN), 256, smemCkv>>>(Kb, Vb, Mb);
    kv_scan_k<<<dim3(16, BHN), 256>>>(Mb, KVb);
    attn_mma_k<<<dim3(NCH, BHN), 256, smemAttn>>>(Q, Kb, Vb, KVb, Ob);

    // layernorm * gate (rounded), final projection
    ln_gate_k<<<MDIM, 256>>>(Ob, GATE, gamma, beta, Ob);
    tgemm3_k<0, 128, false><<<gBig, tB, smem128>>>(Ob, WoT, out, MDIM, EDIM, EDIM);
}

// round 10
// speedup vs baseline: 5.6511x; 1.8271x over previous
#include <cuda_runtime.h>
#include <cuda_fp16.h>
#include <math.h>
#include <stdint.h>

// Problem constants
#define MDIM 16384          // B*N = 2*8192 rows
#define EDIM 1024           // embed
#define DH   64             // head dim
#define NCH  64             // chunks per sequence (8192/128)
#define BHN  32             // B*H
#define QKVN 3072           // fused projection width

// ---------------- scratch (device globals) ----------------------------------
__device__ __half hX[MDIM * EDIM];
__device__ __half hWqkv[EDIM * QKVN];     // [k][n] concat Wq|Wk|Wv
__device__ __half hWo[EDIM * EDIM];       // [k][n]
__device__ __half hWg1[EDIM * DH];        // [k][n]
__device__ __half hWg2[DH * EDIM];        // [k][n]
__device__ __half hQKV[MDIM * QKVN];      // fused silu(xW) outputs
__device__ __half hG1[MDIM * DH];
__device__ __half hGATE[MDIM * EDIM];
__device__ __half hO[MDIM * EDIM];
__device__ __half hOLN[MDIM * EDIM];
__device__ float gM[BHN * NCH * DH * DH];
__device__ float gKV[BHN * NCH * DH * DH];

__device__ __forceinline__ float head_slope(int h) {
    return exp2f(-0.5f * (float)(h + 1)) * 1.00001f;
}

template <int EPI>
__device__ __forceinline__ float epilogue(float v) {
    if (EPI == 1) return v / (1.f + expf(-v));      // silu
    if (EPI == 2) return 1.f / (1.f + expf(-v));    // sigmoid
    return v;
}

#define MMA_F16(acc, a0, a1, a2, a3, b0, b1) \
    asm volatile( \
        "mma.sync.aligned.m16n8k16.row.col.f32.f16.f16.f32 " \
        "{%0,%1,%2,%3}, {%4,%5,%6,%7}, {%8,%9}, {%0,%1,%2,%3};\n" \
        : "+f"((acc)[0]), "+f"((acc)[1]), "+f"((acc)[2]), "+f"((acc)[3]) \
        : "r"(a0), "r"(a1), "r"(a2), "r"(a3), "r"(b0), "r"(b1))

#define LDSM_X4(r, addr) \
    asm volatile("ldmatrix.sync.aligned.m8n8.x4.shared.b16 {%0,%1,%2,%3}, [%4];" \
        : "=r"((r)[0]), "=r"((r)[1]), "=r"((r)[2]), "=r"((r)[3]) : "r"(addr))
#define LDSM_X2(r, addr) \
    asm volatile("ldmatrix.sync.aligned.m8n8.x2.shared.b16 {%0,%1}, [%2];" \
        : "=r"((r)[0]), "=r"((r)[1]) : "r"(addr))
#define LDSM_X4T(r, addr) \
    asm volatile("ldmatrix.sync.aligned.m8n8.x4.trans.shared.b16 {%0,%1,%2,%3}, [%4];" \
        : "=r"((r)[0]), "=r"((r)[1]), "=r"((r)[2]), "=r"((r)[3]) : "r"(addr))
#define LDSM_X2T(r, addr) \
    asm volatile("ldmatrix.sync.aligned.m8n8.x2.trans.shared.b16 {%0,%1}, [%2];" \
        : "=r"((r)[0]), "=r"((r)[1]) : "r"(addr))

__device__ __forceinline__ void cpa_wait(int keep) {
    if (keep <= 0)      asm volatile("cp.async.wait_group 0;" ::);
    else                asm volatile("cp.async.wait_group 1;" ::);
}

// =================== FP16 mma.sync GEMM =====================================
// C = epi(A @ B). A[M,K] half row-major, B[K,N] half row-major.
// 128 x BN_ x 64 tile, 256 thr (8 warps 2x4), warp tile 64 x (BN_/4),
// A via ldmatrix.x4, B via ldmatrix.x2.trans. 3-stage cp.async.
template <int EPI, int BN_, bool HOUT>
__global__ __launch_bounds__(256, 2) void tgemm_h(
    const __half* __restrict__ A, const __half* __restrict__ B,
    void* __restrict__ Cv, int M, int N, int K)
{
    constexpr int AST = 72;                 // A row stride (halves), 64 + pad
    constexpr int BST = BN_ + 8;            // B row stride (halves)
    constexpr int SA_H = 128 * AST;
    constexpr int SB_H = 64 * BST;
    constexpr int STAGE_H = SA_H + SB_H;
    constexpr int CPR = BN_ / 8;            // 16B chunks per B row
    constexpr int BITER = (64 * CPR) / 256;
    constexpr int NT = BN_ / 32;

    extern __shared__ __half smh[];
    const int tid = threadIdx.x;
    const int lane = tid & 31, wid = tid >> 5;
    const int gid = lane >> 2, tg = lane & 3;
    const int wm = (wid >> 2) * 64;
    const int wn = (wid & 3) * (BN_ / 4);
    const int bm = blockIdx.y << 7;
    const int bn = blockIdx.x * BN_;
    const uint32_t smu = (uint32_t)__cvta_generic_to_shared(smh);
    const int KT = K >> 6;                  // 64 halves per k-tile

    const int arow = lane & 15;
    const int acol = (lane >> 4) << 3;      // 0 or 8 halves

    auto fill = [&](int kt) {
        const uint32_t sa = smu + (uint32_t)((kt % 3) * STAGE_H) * 2u;
        const uint32_t sb = sa + (uint32_t)SA_H * 2u;
#pragma unroll
        for (int i = 0; i < 4; i++) {
            const int idx = tid + (i << 8);
            const int row = idx >> 3, ch = idx & 7;
            const __half* src = A + (size_t)(bm + row) * K + (kt << 6) + (ch << 3);
            asm volatile("cp.async.cg.shared.global [%0], [%1], 16;"
                         :: "r"(sa + (uint32_t)(row * AST + (ch << 3)) * 2u), "l"(src));
        }
#pragma unroll
        for (int i = 0; i < BITER; i++) {
            const int idx = tid + (i << 8);
            const int row = idx / CPR, ch = idx % CPR;
            const __half* src = B + (size_t)((kt << 6) + row) * N + bn + (ch << 3);
            asm volatile("cp.async.cg.shared.global [%0], [%1], 16;"
                         :: "r"(sb + (uint32_t)(row * BST + (ch << 3)) * 2u), "l"(src));
        }
        asm volatile("cp.async.commit_group;");
    };

    float acc[4][NT][4];
#pragma unroll
    for (int i = 0; i < 4; i++)
#pragma unroll
        for (int j = 0; j < NT; j++)
#pragma unroll
            for (int q = 0; q < 4; q++) acc[i][j][q] = 0.f;

    fill(0);
    if (KT > 1) fill(1);

    for (int kt = 0; kt < KT; ++kt) {
        cpa_wait((kt + 1 < KT) ? 1 : 0);
        __syncthreads();
        if (kt + 2 < KT) fill(kt + 2);

        const uint32_t sa = smu + (uint32_t)((kt % 3) * STAGE_H) * 2u;
        const uint32_t sb = sa + (uint32_t)SA_H * 2u;
#pragma unroll
        for (int ks = 0; ks < 4; ++ks) {
            const int k0 = ks << 4;
            uint32_t af[4][4], bf[NT][2];
#pragma unroll
            for (int mt = 0; mt < 4; mt++)
                LDSM_X4(af[mt], sa + (uint32_t)((wm + mt * 16 + arow) * AST + k0 + acol) * 2u);
            // B rows are k; trans load from [k][n]
            const int krow = k0 + (lane & 7) + ((lane >> 3) & 1) * 8;
#pragma unroll
            for (int nt = 0; nt < NT; nt++)
                LDSM_X2T(bf[nt], sb + (uint32_t)(krow * BST + wn + nt * 8) * 2u);
#pragma unroll
            for (int mt = 0; mt < 4; mt++)
#pragma unroll
                for (int nt = 0; nt < NT; nt++)
                    MMA_F16(acc[mt][nt], af[mt][0], af[mt][1], af[mt][2], af[mt][3],
                            bf[nt][0], bf[nt][1]);
        }
    }

#pragma unroll
    for (int mt = 0; mt < 4; mt++) {
#pragma unroll
        for (int nt = 0; nt < NT; nt++) {
            const int r0 = bm + wm + mt * 16 + gid;
            const int c = bn + wn + nt * 8 + 2 * tg;
            float e0 = epilogue<EPI>(acc[mt][nt][0]);
            float e1 = epilogue<EPI>(acc[mt][nt][1]);
            float e2 = epilogue<EPI>(acc[mt][nt][2]);
            float e3 = epilogue<EPI>(acc[mt][nt][3]);
            if (HOUT) {
                __half* C = (__half*)Cv;
                *(__half2*)(C + (size_t)r0 * N + c) = __floats2half2_rn(e0, e1);
                *(__half2*)(C + (size_t)(r0 + 8) * N + c) = __floats2half2_rn(e2, e3);
            } else {
                float* C = (float*)Cv;
                *(float2*)(C + (size_t)r0 * N + c) = make_float2(e0, e1);
                *(float2*)(C + (size_t)(r0 + 8) * N + c) = make_float2(e2, e3);
            }
        }
    }
}

// ---------------- prep: fp32 -> fp16 converts --------------------------------
__global__ __launch_bounds__(256) void cvt_half_k(
    const float4* __restrict__ in, __half* __restrict__ out)
{
    const int i = blockIdx.x * 256 + threadIdx.x;
    float4 v = in[i];
    __half2* o = (__half2*)(out + (size_t)i * 4);
    o[0] = __floats2half2_rn(v.x, v.y);
    o[1] = __floats2half2_rn(v.z, v.w);
}

// W [1024][1024] fp32 -> dst[k][off + n] within [1024][3072] half
__global__ __launch_bounds__(256) void cvt_qkv_k(
    const float* __restrict__ src, __half* __restrict__ dst, int off)
{
    const int i4 = blockIdx.x * 256 + threadIdx.x;     // float4 index
    const int k = i4 >> 8, n4 = (i4 & 255) << 2;
    float4 v = *(const float4*)(src + (size_t)k * 1024 + n4);
    __half2* o = (__half2*)(dst + (size_t)k * QKVN + off + n4);
    o[0] = __floats2half2_rn(v.x, v.y);
    o[1] = __floats2half2_rn(v.z, v.w);
}

// ------------- pass A (fp16 mma): M = K^T diag(lamk) V  [64x64] -------------
// smem: dpw f32[136] | Ks[128][72] h | Vs[128][72] h  (natural [j][feat])
__global__ __launch_bounds__(256) void ckv_h_k(
    const __half* __restrict__ QKV, float* __restrict__ Mo)
{
    extern __shared__ char smc[];
    float* dpw = (float*)smc;
    __half* Ks = (__half*)(smc + 544);
    __half* Vs = Ks + 128 * 72;
    const uint32_t smb = (uint32_t)__cvta_generic_to_shared(smc);
    const uint32_t kB = smb + 544;
    const uint32_t vB = kB + 128 * 72 * 2;

    const int c = blockIdx.x, bh = blockIdx.y;
    const int b = bh >> 4, h = bh & 15;
    const int tid = threadIdx.x;
    const int lane = tid & 31, wid = tid >> 5;
    const int gid = lane >> 2, tg = lane & 3;
    const float s = head_slope(h);
    if (tid < 129) dpw[tid] = expf(-s * (float)tid);
    __syncthreads();

    const size_t rowbase = (size_t)b * 8192 + (size_t)c * 128;
    const int colbase = h * 64;

    // K scaled by lamk (fp32 math, rn to half); V plain copy
#pragma unroll
    for (int i = 0; i < 16; ++i) {
        const int idx = tid + (i << 8);            // half2 slots: 4096
        const int j = idx >> 5, c2 = (idx & 31) << 1;
        const __half2 kv2 = *(const __half2*)(QKV + (rowbase + j) * QKVN + 1024 + colbase + c2);
        const float lk = dpw[127 - j];
        float2 f = __half22float2(kv2);
        *(__half2*)(Ks + j * 72 + c2) = __floats2half2_rn(f.x * lk, f.y * lk);
    }
#pragma unroll
    for (int i = 0; i < 4; ++i) {
        const int idx = tid + (i << 8);            // 16B chunks: 1024
        const int j = idx >> 3, ch = (idx & 7) << 3;
        *(uint4*)(Vs + j * 72 + ch) =
            *(const uint4*)(QKV + (rowbase + j) * QKVN + 2048 + colbase + ch);
    }
    __syncthreads();

    // m=d (64), n=e (64), k=j (128). A=K^T via trans-x4, B=V^T via trans-x2.
    const int wm = (wid >> 2) * 32;
    const int wn = (wid & 3) * 16;
    float acc[2][2][4];
#pragma unroll
    for (int i = 0; i < 2; i++)
#pragma unroll
        for (int j = 0; j < 2; j++)
#pragma unroll
            for (int q = 0; q < 4; q++) acc[i][j][q] = 0.f;

#pragma unroll
    for (int ks = 0; ks < 8; ++ks) {
        const int k0 = ks << 4;
        uint32_t af[2][4], bf[2][2];
        const int akr = k0 + ((lane >> 4) << 3) + (lane & 7);
        const int amc = ((lane >> 3) & 1) << 3;
        const int bkr = k0 + (lane & 7) + (((lane >> 3) & 1) << 3);
#pragma unroll
        for (int mt = 0; mt < 2; mt++)
            LDSM_X4T(af[mt], kB + (uint32_t)(akr * 72 + wm + mt * 16 + amc) * 2u);
#pragma unroll
        for (int nt = 0; nt < 2; nt++)
            LDSM_X2T(bf[nt], vB + (uint32_t)(bkr * 72 + wn + nt * 8) * 2u);
#pragma unroll
        for (int mt = 0; mt < 2; mt++)
#pragma unroll
            for (int nt = 0; nt < 2; nt++)
                MMA_F16(acc[mt][nt], af[mt][0], af[mt][1], af[mt][2], af[mt][3],
                        bf[nt][0], bf[nt][1]);
    }

    float* out = Mo + ((size_t)bh * NCH + c) * 4096;
#pragma unroll
    for (int mt = 0; mt < 2; mt++) {
#pragma unroll
        for (int nt = 0; nt < 2; nt++) {
            const int i0 = wm + mt * 16 + gid;
            const int j0 = wn + nt * 8 + 2 * tg;
            *(float2*)(out + i0 * 64 + j0) = make_float2(acc[mt][nt][0], acc[mt][nt][1]);
            *(float2*)(out + (i0 + 8) * 64 + j0) = make_float2(acc[mt][nt][2], acc[mt][nt][3]);
        }
    }
}

// ------------- pass B: decayed prefix scan of M over chunks -----------------
__global__ __launch_bounds__(256) void kv_scan_k(
    const float* __restrict__ Mi, float* __restrict__ KVo)
{
    const int bh = blockIdx.y;
    const int elem = blockIdx.x * 256 + threadIdx.x;
    const int h = bh & 15;
    const float s = head_slope(h);
    const float lamc = expf(-s * 128.f);

    float acc = 0.f;
    const size_t base = (size_t)bh * NCH * 4096 + elem;
    for (int c = 0; c < NCH; ++c) {
        const size_t idx = base + (size_t)c * 4096;
        KVo[idx] = acc;
        acc = fmaf(lamc, acc, Mi[idx]);
    }
}

// ------------- pass C (fp16 mma): O = (mask o QK^T) V + lamq o (Q KV) -------
// smem: dpw f32[136] | Qs[128][72] | Ks/Vs[128][72] | KVs[64][72] | Ss[128][136]
__global__ __launch_bounds__(256) void attn_h_k(
    const __half* __restrict__ QKV, const float* __restrict__ KVi,
    __half* __restrict__ Og)
{
    extern __shared__ char smc[];
    float* dpw = (float*)smc;
    __half* Qs = (__half*)(smc + 544);
    __half* Ks = Qs + 128 * 72;
    __half* KVs = Ks + 128 * 72;
    __half* Ss = KVs + 64 * 72;
    const uint32_t smb = (uint32_t)__cvta_generic_to_shared(smc);
    const uint32_t qB = smb + 544;
    const uint32_t kB = qB + 128 * 72 * 2;
    const uint32_t kvB = kB + 128 * 72 * 2;
    const uint32_t sB = kvB + 64 * 72 * 2;

    const int c = blockIdx.x, bh = blockIdx.y;
    const int b = bh >> 4, h = bh & 15;
    const int tid = threadIdx.x;
    const int lane = tid & 31, wid = tid >> 5;
    const int gid = lane >> 2, tg = lane & 3;
    const int arow = lane & 15;
    const int acol = (lane >> 4) << 3;
    const int brow = lane & 7;
    const int bcol = ((lane >> 3) & 1) << 3;
    const float s = head_slope(h);
    if (tid < 129) dpw[tid] = expf(-s * (float)tid);

    const size_t rowbase = (size_t)b * 8192 + (size_t)c * 128;
    const int colbase = h * 64;

    // Q and K rows (natural [i][d]); KV fp32 -> half [d][e]
#pragma unroll
    for (int i = 0; i < 4; ++i) {
        const int idx = tid + (i << 8);
        const int r = idx >> 3, ch = (idx & 7) << 3;
        const size_t g = (rowbase + r) * QKVN + colbase + ch;
        *(uint4*)(Qs + r * 72 + ch) = *(const uint4*)(QKV + g);
        *(uint4*)(Ks + r * 72 + ch) = *(const uint4*)(QKV + g + 1024);
    }
    {
        const float* kvsrc = KVi + ((size_t)bh * NCH + c) * 4096;
#pragma unroll
        for (int i = 0; i < 8; ++i) {
            const int idx = tid + (i << 8);          // float2 slots: 2048
            const int d = idx >> 5, e2 = (idx & 31) << 1;
            float2 f = *(const float2*)(kvsrc + d * 64 + e2);
            *(__half2*)(KVs + d * 72 + e2) = __floats2half2_rn(f.x, f.y);
        }
    }
    __syncthreads();

    // merged phase 1+3: S = Q K^T (64x32), oc = Q KV (64x16); k = d over 64
    const int wmS = (wid >> 2) * 64, wnS = (wid & 3) * 32;
    const int wnO = (wid & 3) * 16;
    float sc[4][4][4];
    float oc[4][2][4];
#pragma unroll
    for (int i = 0; i < 4; i++) {
#pragma unroll
        for (int j = 0; j < 4; j++)
#pragma unroll
            for (int q = 0; q < 4; q++) sc[i][j][q] = 0.f;
#pragma unroll
        for (int j = 0; j < 2; j++)
#pragma unroll
            for (int q = 0; q < 4; q++) oc[i][j][q] = 0.f;
    }

#pragma unroll
    for (int ks = 0; ks < 4; ++ks) {
        const int k0 = ks << 4;
        uint32_t af[4][4], bf[4][2], bk[2][2];
#pragma unroll
        for (int mt = 0; mt < 4; mt++)
            LDSM_X4(af[mt], qB + (uint32_t)((wmS + mt * 16 + arow) * 72 + k0 + acol) * 2u);
#pragma unroll
        for (int nt = 0; nt < 4; nt++)       // B = Ks [n=j][k=d], non-trans
            LDSM_X2(bf[nt], kB + (uint32_t)((wnS + nt * 8 + brow) * 72 + k0 + bcol) * 2u);
        const int kvr = k0 + (lane & 7) + (((lane >> 3) & 1) << 3);
#pragma unroll
        for (int nt = 0; nt < 2; nt++)       // B = KVs [k=d][n=e], trans
            LDSM_X2T(bk[nt], kvB + (uint32_t)(kvr * 72 + wnO + nt * 8) * 2u);
#pragma unroll
        for (int mt = 0; mt < 4; mt++) {
#pragma unroll
            for (int nt = 0; nt < 4; nt++)
                MMA_F16(sc[mt][nt], af[mt][0], af[mt][1], af[mt][2], af[mt][3],
                        bf[nt][0], bf[nt][1]);
#pragma unroll
            for (int nt = 0; nt < 2; nt++)
                MMA_F16(oc[mt][nt], af[mt][0], af[mt][1], af[mt][2], af[mt][3],
                        bk[nt][0], bk[nt][1]);
        }
    }

    // mask + decay, write S to smem (half)
#pragma unroll
    for (int mt = 0; mt < 4; mt++) {
#pragma unroll
        for (int nt = 0; nt < 4; nt++) {
            const int i0 = wmS + mt * 16 + gid;
            const int j0 = wnS + nt * 8 + 2 * tg;
            const int d00 = i0 - j0;
            float v0 = (d00 >= 0) ? sc[mt][nt][0] * dpw[d00] : 0.f;
            float v1 = (d00 >= 1) ? sc[mt][nt][1] * dpw[d00 - 1] : 0.f;
            float v2 = (d00 >= -8) ? sc[mt][nt][2] * dpw[d00 + 8] : 0.f;
            float v3 = (d00 >= -7) ? sc[mt][nt][3] * dpw[d00 + 7] : 0.f;
            *(__half2*)(Ss + i0 * 136 + j0) = __floats2half2_rn(v0, v1);
            *(__half2*)(Ss + (i0 + 8) * 136 + j0) = __floats2half2_rn(v2, v3);
        }
    }

    // scale oc by lamq[i] = dpw[i+1]
#pragma unroll
    for (int mt = 0; mt < 4; mt++) {
        const int i0 = wmS + mt * 16 + gid;
        const float l0 = dpw[i0 + 1], l1 = dpw[i0 + 9];
#pragma unroll
        for (int nt = 0; nt < 2; nt++) {
            oc[mt][nt][0] *= l0; oc[mt][nt][1] *= l0;
            oc[mt][nt][2] *= l1; oc[mt][nt][3] *= l1;
        }
    }

    __syncthreads();      // S written; K/KV reads done

    // V rows into Ks region (natural [j][e])
#pragma unroll
    for (int i = 0; i < 4; ++i) {
        const int idx = tid + (i << 8);
        const int r = idx >> 3, ch = (idx & 7) << 3;
        *(uint4*)(Ks + r * 72 + ch) =
            *(const uint4*)(QKV + (rowbase + r) * QKVN + 2048 + colbase + ch);
    }
    __syncthreads();

    // phase 2: oc += S @ V.  A = Ss [i][j] x4; B = Vs [k=j][n=e] trans-x2.
#pragma unroll
    for (int ks = 0; ks < 8; ++ks) {
        const int k0 = ks << 4;
        uint32_t af[4][4], bf[2][2];
#pragma unroll
        for (int mt = 0; mt < 4; mt++)
            LDSM_X4(af[mt], sB + (uint32_t)((wmS + mt * 16 + arow) * 136 + k0 + acol) * 2u);
        const int vkr = k0 + (lane & 7) + (((lane >> 3) & 1) << 3);
#pragma unroll
        for (int nt = 0; nt < 2; nt++)
            LDSM_X2T(bf[nt], kB + (uint32_t)(vkr * 72 + wnO + nt * 8) * 2u);
#pragma unroll
        for (int mt = 0; mt < 4; mt++)
#pragma unroll
            for (int nt = 0; nt < 2; nt++)
                MMA_F16(oc[mt][nt], af[mt][0], af[mt][1], af[mt][2], af[mt][3],
                        bf[nt][0], bf[nt][1]);
    }

    // write O (half)
#pragma unroll
    for (int mt = 0; mt < 4; mt++) {
#pragma unroll
        for (int nt = 0; nt < 2; nt++) {
            const int i0 = wmS + mt * 16 + gid;
            const int e0 = wnO + nt * 8 + 2 * tg;
            *(__half2*)(Og + (rowbase + i0) * 1024 + colbase + e0) =
                __floats2half2_rn(oc[mt][nt][0], oc[mt][nt][1]);
            *(__half2*)(Og + (rowbase + i0 + 8) * 1024 + colbase + e0) =
                __floats2half2_rn(oc[mt][nt][2], oc[mt][nt][3]);
        }
    }
}

// ------------- LayerNorm * gate (half in, half out) -------------------------
__global__ __launch_bounds__(256) void ln_gate_h(
    const __half* __restrict__ O, const __half* __restrict__ G,
    const float* __restrict__ gamma, const float* __restrict__ beta,
    __half* __restrict__ OLN)
{
    __shared__ float red[2][8];
    const int row = blockIdx.x, tid = threadIdx.x;
    const size_t base = (size_t)row * 1024 + (tid << 2);
    float2 a = __half22float2(*(const __half2*)(O + base));
    float2 bb = __half22float2(*(const __half2*)(O + base + 2));
    float sum = a.x + a.y + bb.x + bb.y;
    float sq = a.x * a.x + a.y * a.y + bb.x * bb.x + bb.y * bb.y;
#pragma unroll
    for (int o = 16; o > 0; o >>= 1) {
        sum += __shfl_xor_sync(0xffffffff, sum, o);
        sq += __shfl_xor_sync(0xffffffff, sq, o);
    }
    if ((tid & 31) == 0) { red[0][tid >> 5] = sum; red[1][tid >> 5] = sq; }
    __syncthreads();
    float ts = 0.f, tq = 0.f;
#pragma unroll
    for (int w = 0; w < 8; w++) { ts += red[0][w]; tq += red[1][w]; }
    const float mu = ts * (1.f / 1024.f);
    const float var = tq * (1.f / 1024.f) - mu * mu;
    const float rstd = rsqrtf(var + 1e-5f);

    float4 g4 = *(const float4*)(gamma + (tid << 2));
    float4 b4 = *(const float4*)(beta + (tid << 2));
    float2 gt0 = __half22float2(*(const __half2*)(G + base));
    float2 gt1 = __half22float2(*(const __half2*)(G + base + 2));
    float o0 = ((a.x - mu) * rstd * g4.x + b4.x) * gt0.x;
    float o1 = ((a.y - mu) * rstd * g4.y + b4.y) * gt0.y;
    float o2 = ((bb.x - mu) * rstd * g4.z + b4.z) * gt1.x;
    float o3 = ((bb.y - mu) * rstd * g4.w + b4.w) * gt1.y;
    *(__half2*)(OLN + base) = __floats2half2_rn(o0, o1);
    *(__half2*)(OLN + base + 2) = __floats2half2_rn(o2, o3);
}

// ---------------------------------------------------------------------------
extern "C" void kernel_launch(void* const* d_in, const int* in_sizes, int n_in,
                              void* d_out, int out_size)
{
    const float* x     = (const float*)d_in[0];
    const float* Wq    = (const float*)d_in[1];
    const float* Wk    = (const float*)d_in[2];
    const float* Wv    = (const float*)d_in[3];
    const float* Wo    = (const float*)d_in[4];
    const float* gamma = (const float*)d_in[5];
    const float* beta  = (const float*)d_in[6];
    const float* Wg1   = (const float*)d_in[7];
    const float* Wg2   = (const float*)d_in[8];
    float* out = (float*)d_out;

    void *pX, *pWqkv, *pWo, *pWg1, *pWg2, *pQKV, *pG1, *pGATE, *pO, *pOLN, *pM, *pKV;
    cudaGetSymbolAddress(&pX, hX);
    cudaGetSymbolAddress(&pWqkv, hWqkv);
    cudaGetSymbolAddress(&pWo, hWo);
    cudaGetSymbolAddress(&pWg1, hWg1);
    cudaGetSymbolAddress(&pWg2, hWg2);
    cudaGetSymbolAddress(&pQKV, hQKV);
    cudaGetSymbolAddress(&pG1, hG1);
    cudaGetSymbolAddress(&pGATE, hGATE);
    cudaGetSymbolAddress(&pO, hO);
    cudaGetSymbolAddress(&pOLN, hOLN);
    cudaGetSymbolAddress(&pM, gM);
    cudaGetSymbolAddress(&pKV, gKV);
    __half* X = (__half*)pX;       __half* Wqkv = (__half*)pWqkv;
    __half* WoH = (__half*)pWo;    __half* Wg1H = (__half*)pWg1;
    __half* Wg2H = (__half*)pWg2;  __half* QKV = (__half*)pQKV;
    __half* G1 = (__half*)pG1;     __half* GATE = (__half*)pGATE;
    __half* O = (__half*)pO;       __half* OLN = (__half*)pOLN;
    float* Mb = (float*)pM;        float* KVb = (float*)pKV;

    // smem sizes
    const int smG128 = 3 * (128 * 72 + 64 * 136) * 2;   // 107520
    const int smG64  = 3 * (128 * 72 + 64 * 72) * 2;    //  82944
    const int smAttn = 544 + (128 * 72 + 128 * 72 + 64 * 72 + 128 * 136) * 2;
    const int smCkv  = 544 + (128 * 72 + 128 * 72) * 2;
    cudaFuncSetAttribute(tgemm_h<1, 128, true>,
                         cudaFuncAttributeMaxDynamicSharedMemorySize, smG128);
    cudaFuncSetAttribute(tgemm_h<2, 128, true>,
                         cudaFuncAttributeMaxDynamicSharedMemorySize, smG128);
    cudaFuncSetAttribute(tgemm_h<0, 128, false>,
                         cudaFuncAttributeMaxDynamicSharedMemorySize, smG128);
    cudaFuncSetAttribute(tgemm_h<0, 64, true>,
                         cudaFuncAttributeMaxDynamicSharedMemorySize, smG64);
    cudaFuncSetAttribute(attn_h_k,
                         cudaFuncAttributeMaxDynamicSharedMemorySize, smAttn);
    cudaFuncSetAttribute(ckv_h_k,
                         cudaFuncAttributeMaxDynamicSharedMemorySize, smCkv);

    // ---- prep: convert to fp16 ----
    cvt_half_k<<<MDIM * EDIM / 1024, 256>>>((const float4*)x, X);
    cvt_qkv_k<<<1024, 256>>>(Wq, Wqkv, 0);
    cvt_qkv_k<<<1024, 256>>>(Wk, Wqkv, 1024);
    cvt_qkv_k<<<1024, 256>>>(Wv, Wqkv, 2048);
    cvt_half_k<<<EDIM * EDIM / 1024, 256>>>((const float4*)Wo, WoH);
    cvt_half_k<<<EDIM * DH / 1024, 256>>>((const float4*)Wg1, Wg1H);
    cvt_half_k<<<EDIM * DH / 1024, 256>>>((const float4*)Wg2, Wg2H);

    dim3 tB(256);

    // fused QKV projection: [M,3072] = silu(X @ Wqkv)
    tgemm_h<1, 128, true><<<dim3(QKVN / 128, MDIM / 128), tB, smG128>>>(
        X, Wqkv, QKV, MDIM, QKVN, EDIM);

    // gate path
    tgemm_h<0, 64, true><<<dim3(1, MDIM / 128), tB, smG64>>>(
        X, Wg1H, G1, MDIM, DH, EDIM);
    tgemm_h<2, 128, true><<<dim3(EDIM / 128, MDIM / 128), tB, smG128>>>(
        G1, Wg2H, GATE, MDIM, EDIM, DH);

    // attention
    ckv_h_k<<<dim3(NCH, BHN), tB, smCkv>>>(QKV, Mb);
    kv_scan_k<<<dim3(16, BHN), tB>>>(Mb, KVb);
    attn_h_k<<<dim3(NCH, BHN), tB, smAttn>>>(QKV, KVb, O);

    // layernorm * gate, final projection (fp32 out)
    ln_gate_h<<<MDIM, tB>>>(O, GATE, gamma, beta, OLN);
    tgemm_h<0, 128, false><<<dim3(EDIM / 128, MDIM / 128), tB, smG128>>>(
        OLN, WoH, out, MDIM, EDIM, EDIM);
}

// round 11
// speedup vs baseline: 5.8218x; 1.0302x over previous
#include <cuda_runtime.h>
#include <cuda_fp16.h>
#include <math.h>
#include <stdint.h>

// Problem constants
#define MDIM 16384          // B*N = 2*8192 rows
#define EDIM 1024           // embed
#define DH   64             // head dim
#define NCH  64             // chunks per sequence (8192/128)
#define BHN  32             // B*H
#define QKVN 3072           // fused projection width

// ---------------- scratch (device globals) ----------------------------------
__device__ __half hX[MDIM * EDIM];
__device__ __half hWqkv[EDIM * QKVN];     // [k][n] concat Wq|Wk|Wv
__device__ __half hWo[EDIM * EDIM];       // [k][n]
__device__ __half hWg1[EDIM * DH];        // [k][n]
__device__ __half hWg2[DH * EDIM];        // [k][n]
__device__ __half hQKV[MDIM * QKVN];      // fused silu(xW) outputs
__device__ __half hG1[MDIM * DH];
__device__ __half hGATE[MDIM * EDIM];
__device__ __half hO[MDIM * EDIM];
__device__ __half hOLN[MDIM * EDIM];
__device__ float gM[BHN * NCH * DH * DH];
__device__ float gKV[BHN * NCH * DH * DH];

__device__ __forceinline__ float head_slope(int h) {
    return exp2f(-0.5f * (float)(h + 1)) * 1.00001f;
}

template <int EPI>
__device__ __forceinline__ float epilogue(float v) {
    if (EPI == 1) {                       // silu (fast-math)
        const float e = __expf(-v);
        return __fdividef(v, 1.f + e);
    }
    if (EPI == 2) {                       // sigmoid (fast-math)
        const float e = __expf(-v);
        return __fdividef(1.f, 1.f + e);
    }
    return v;
}

#define MMA_F16(acc, a0, a1, a2, a3, b0, b1) \
    asm volatile( \
        "mma.sync.aligned.m16n8k16.row.col.f32.f16.f16.f32 " \
        "{%0,%1,%2,%3}, {%4,%5,%6,%7}, {%8,%9}, {%0,%1,%2,%3};\n" \
        : "+f"((acc)[0]), "+f"((acc)[1]), "+f"((acc)[2]), "+f"((acc)[3]) \
        : "r"(a0), "r"(a1), "r"(a2), "r"(a3), "r"(b0), "r"(b1))

#define LDSM_X4(r, addr) \
    asm volatile("ldmatrix.sync.aligned.m8n8.x4.shared.b16 {%0,%1,%2,%3}, [%4];" \
        : "=r"((r)[0]), "=r"((r)[1]), "=r"((r)[2]), "=r"((r)[3]) : "r"(addr))
#define LDSM_X2(r, addr) \
    asm volatile("ldmatrix.sync.aligned.m8n8.x2.shared.b16 {%0,%1}, [%2];" \
        : "=r"((r)[0]), "=r"((r)[1]) : "r"(addr))
#define LDSM_X4T(r, addr) \
    asm volatile("ldmatrix.sync.aligned.m8n8.x4.trans.shared.b16 {%0,%1,%2,%3}, [%4];" \
        : "=r"((r)[0]), "=r"((r)[1]), "=r"((r)[2]), "=r"((r)[3]) : "r"(addr))
#define LDSM_X2T(r, addr) \
    asm volatile("ldmatrix.sync.aligned.m8n8.x2.trans.shared.b16 {%0,%1}, [%2];" \
        : "=r"((r)[0]), "=r"((r)[1]) : "r"(addr))

__device__ __forceinline__ void cpa_wait(int keep) {
    if (keep <= 0)      asm volatile("cp.async.wait_group 0;" ::);
    else                asm volatile("cp.async.wait_group 1;" ::);
}

// =================== FP16 mma.sync GEMM =====================================
// C = epi(A @ B). A[M,K] half row-major, B[K,N] half row-major.
// 128 x BN_ x 64 tile, 256 thr (8 warps 2x4), warp tile 64 x (BN_/4),
// A via ldmatrix.x4, B via ldmatrix.x2.trans. 3-stage cp.async.
template <int EPI, int BN_, bool HOUT>
__global__ __launch_bounds__(256, 2) void tgemm_h(
    const __half* __restrict__ A, const __half* __restrict__ B,
    void* __restrict__ Cv, int M, int N, int K)
{
    constexpr int AST = 72;                 // A row stride (halves), 64 + pad
    constexpr int BST = BN_ + 8;            // B row stride (halves)
    constexpr int SA_H = 128 * AST;
    constexpr int SB_H = 64 * BST;
    constexpr int STAGE_H = SA_H + SB_H;
    constexpr int CPR = BN_ / 8;            // 16B chunks per B row
    constexpr int BITER = (64 * CPR) / 256;
    constexpr int NT = BN_ / 32;

    extern __shared__ __half smh[];
    const int tid = threadIdx.x;
    const int lane = tid & 31, wid = tid >> 5;
    const int gid = lane >> 2, tg = lane & 3;
    const int wm = (wid >> 2) * 64;
    const int wn = (wid & 3) * (BN_ / 4);
    const int bm = blockIdx.y << 7;
    const int bn = blockIdx.x * BN_;
    const uint32_t smu = (uint32_t)__cvta_generic_to_shared(smh);
    const int KT = K >> 6;                  // 64 halves per k-tile

    const int arow = lane & 15;
    const int acol = (lane >> 4) << 3;      // 0 or 8 halves

    auto fill = [&](int kt) {
        const uint32_t sa = smu + (uint32_t)((kt % 3) * STAGE_H) * 2u;
        const uint32_t sb = sa + (uint32_t)SA_H * 2u;
#pragma unroll
        for (int i = 0; i < 4; i++) {
            const int idx = tid + (i << 8);
            const int row = idx >> 3, ch = idx & 7;
            const __half* src = A + (size_t)(bm + row) * K + (kt << 6) + (ch << 3);
            asm volatile("cp.async.cg.shared.global [%0], [%1], 16;"
                         :: "r"(sa + (uint32_t)(row * AST + (ch << 3)) * 2u), "l"(src));
        }
#pragma unroll
        for (int i = 0; i < BITER; i++) {
            const int idx = tid + (i << 8);
            const int row = idx / CPR, ch = idx % CPR;
            const __half* src = B + (size_t)((kt << 6) + row) * N + bn + (ch << 3);
            asm volatile("cp.async.cg.shared.global [%0], [%1], 16;"
                         :: "r"(sb + (uint32_t)(row * BST + (ch << 3)) * 2u), "l"(src));
        }
        asm volatile("cp.async.commit_group;");
    };

    float acc[4][NT][4];
#pragma unroll
    for (int i = 0; i < 4; i++)
#pragma unroll
        for (int j = 0; j < NT; j++)
#pragma unroll
            for (int q = 0; q < 4; q++) acc[i][j][q] = 0.f;

    fill(0);
    if (KT > 1) fill(1);

    for (int kt = 0; kt < KT; ++kt) {
        cpa_wait((kt + 1 < KT) ? 1 : 0);
        __syncthreads();
        if (kt + 2 < KT) fill(kt + 2);

        const uint32_t sa = smu + (uint32_t)((kt % 3) * STAGE_H) * 2u;
        const uint32_t sb = sa + (uint32_t)SA_H * 2u;
#pragma unroll
        for (int ks = 0; ks < 4; ++ks) {
            const int k0 = ks << 4;
            uint32_t af[4][4], bf[NT][2];
#pragma unroll
            for (int mt = 0; mt < 4; mt++)
                LDSM_X4(af[mt], sa + (uint32_t)((wm + mt * 16 + arow) * AST + k0 + acol) * 2u);
            // B rows are k; trans load from [k][n]
            const int krow = k0 + (lane & 7) + ((lane >> 3) & 1) * 8;
#pragma unroll
            for (int nt = 0; nt < NT; nt++)
                LDSM_X2T(bf[nt], sb + (uint32_t)(krow * BST + wn + nt * 8) * 2u);
#pragma unroll
            for (int mt = 0; mt < 4; mt++)
#pragma unroll
                for (int nt = 0; nt < NT; nt++)
                    MMA_F16(acc[mt][nt], af[mt][0], af[mt][1], af[mt][2], af[mt][3],
                            bf[nt][0], bf[nt][1]);
        }
    }

#pragma unroll
    for (int mt = 0; mt < 4; mt++) {
#pragma unroll
        for (int nt = 0; nt < NT; nt++) {
            const int r0 = bm + wm + mt * 16 + gid;
            const int c = bn + wn + nt * 8 + 2 * tg;
            float e0 = epilogue<EPI>(acc[mt][nt][0]);
            float e1 = epilogue<EPI>(acc[mt][nt][1]);
            float e2 = epilogue<EPI>(acc[mt][nt][2]);
            float e3 = epilogue<EPI>(acc[mt][nt][3]);
            if (HOUT) {
                __half* C = (__half*)Cv;
                *(__half2*)(C + (size_t)r0 * N + c) = __floats2half2_rn(e0, e1);
                *(__half2*)(C + (size_t)(r0 + 8) * N + c) = __floats2half2_rn(e2, e3);
            } else {
                float* C = (float*)Cv;
                *(float2*)(C + (size_t)r0 * N + c) = make_float2(e0, e1);
                *(float2*)(C + (size_t)(r0 + 8) * N + c) = make_float2(e2, e3);
            }
        }
    }
}

// ---------------- prep: fp32 -> fp16 converts --------------------------------
__global__ __launch_bounds__(256) void cvt_half_k(
    const float4* __restrict__ in, __half* __restrict__ out)
{
    const int i = blockIdx.x * 256 + threadIdx.x;
    float4 v = in[i];
    __half2* o = (__half2*)(out + (size_t)i * 4);
    o[0] = __floats2half2_rn(v.x, v.y);
    o[1] = __floats2half2_rn(v.z, v.w);
}

// W [1024][1024] fp32 -> dst[k][off + n] within [1024][3072] half
__global__ __launch_bounds__(256) void cvt_qkv_k(
    const float* __restrict__ src, __half* __restrict__ dst, int off)
{
    const int i4 = blockIdx.x * 256 + threadIdx.x;     // float4 index
    const int k = i4 >> 8, n4 = (i4 & 255) << 2;
    float4 v = *(const float4*)(src + (size_t)k * 1024 + n4);
    __half2* o = (__half2*)(dst + (size_t)k * QKVN + off + n4);
    o[0] = __floats2half2_rn(v.x, v.y);
    o[1] = __floats2half2_rn(v.z, v.w);
}

// ------------- pass A (fp16 mma): M = K^T diag(lamk) V  [64x64] -------------
// smem: dpw f32[136] | Ks[128][72] h | Vs[128][72] h  (natural [j][feat])
__global__ __launch_bounds__(256) void ckv_h_k(
    const __half* __restrict__ QKV, float* __restrict__ Mo)
{
    extern __shared__ char smc[];
    float* dpw = (float*)smc;
    __half* Ks = (__half*)(smc + 544);
    __half* Vs = Ks + 128 * 72;
    const uint32_t smb = (uint32_t)__cvta_generic_to_shared(smc);
    const uint32_t kB = smb + 544;
    const uint32_t vB = kB + 128 * 72 * 2;

    const int c = blockIdx.x, bh = blockIdx.y;
    const int b = bh >> 4, h = bh & 15;
    const int tid = threadIdx.x;
    const int lane = tid & 31, wid = tid >> 5;
    const int gid = lane >> 2, tg = lane & 3;
    const float s = head_slope(h);
    if (tid < 129) dpw[tid] = __expf(-s * (float)tid);
    __syncthreads();

    const size_t rowbase = (size_t)b * 8192 + (size_t)c * 128;
    const int colbase = h * 64;

    // K scaled by lamk (fp32 math, rn to half); V plain copy
#pragma unroll
    for (int i = 0; i < 16; ++i) {
        const int idx = tid + (i << 8);            // half2 slots: 4096
        const int j = idx >> 5, c2 = (idx & 31) << 1;
        const __half2 kv2 = *(const __half2*)(QKV + (rowbase + j) * QKVN + 1024 + colbase + c2);
        const float lk = dpw[127 - j];
        float2 f = __half22float2(kv2);
        *(__half2*)(Ks + j * 72 + c2) = __floats2half2_rn(f.x * lk, f.y * lk);
    }
#pragma unroll
    for (int i = 0; i < 4; ++i) {
        const int idx = tid + (i << 8);            // 16B chunks: 1024
        const int j = idx >> 3, ch = (idx & 7) << 3;
        *(uint4*)(Vs + j * 72 + ch) =
            *(const uint4*)(QKV + (rowbase + j) * QKVN + 2048 + colbase + ch);
    }
    __syncthreads();

    // m=d (64), n=e (64), k=j (128). A=K^T via trans-x4, B=V^T via trans-x2.
    const int wm = (wid >> 2) * 32;
    const int wn = (wid & 3) * 16;
    float acc[2][2][4];
#pragma unroll
    for (int i = 0; i < 2; i++)
#pragma unroll
        for (int j = 0; j < 2; j++)
#pragma unroll
            for (int q = 0; q < 4; q++) acc[i][j][q] = 0.f;

#pragma unroll
    for (int ks = 0; ks < 8; ++ks) {
        const int k0 = ks << 4;
        uint32_t af[2][4], bf[2][2];
        const int akr = k0 + ((lane >> 4) << 3) + (lane & 7);
        const int amc = ((lane >> 3) & 1) << 3;
        const int bkr = k0 + (lane & 7) + (((lane >> 3) & 1) << 3);
#pragma unroll
        for (int mt = 0; mt < 2; mt++)
            LDSM_X4T(af[mt], kB + (uint32_t)(akr * 72 + wm + mt * 16 + amc) * 2u);
#pragma unroll
        for (int nt = 0; nt < 2; nt++)
            LDSM_X2T(bf[nt], vB + (uint32_t)(bkr * 72 + wn + nt * 8) * 2u);
#pragma unroll
        for (int mt = 0; mt < 2; mt++)
#pragma unroll
            for (int nt = 0; nt < 2; nt++)
                MMA_F16(acc[mt][nt], af[mt][0], af[mt][1], af[mt][2], af[mt][3],
                        bf[nt][0], bf[nt][1]);
    }

    float* out = Mo + ((size_t)bh * NCH + c) * 4096;
#pragma unroll
    for (int mt = 0; mt < 2; mt++) {
#pragma unroll
        for (int nt = 0; nt < 2; nt++) {
            const int i0 = wm + mt * 16 + gid;
            const int j0 = wn + nt * 8 + 2 * tg;
            *(float2*)(out + i0 * 64 + j0) = make_float2(acc[mt][nt][0], acc[mt][nt][1]);
            *(float2*)(out + (i0 + 8) * 64 + j0) = make_float2(acc[mt][nt][2], acc[mt][nt][3]);
        }
    }
}

// ------------- pass B: decayed prefix scan of M over chunks -----------------
__global__ __launch_bounds__(256) void kv_scan_k(
    const float* __restrict__ Mi, float* __restrict__ KVo)
{
    const int bh = blockIdx.y;
    const int elem = blockIdx.x * 256 + threadIdx.x;
    const int h = bh & 15;
    const float s = head_slope(h);
    const float lamc = __expf(-s * 128.f);

    float acc = 0.f;
    const size_t base = (size_t)bh * NCH * 4096 + elem;
    for (int c = 0; c < NCH; ++c) {
        const size_t idx = base + (size_t)c * 4096;
        KVo[idx] = acc;
        acc = fmaf(lamc, acc, Mi[idx]);
    }
}

// ------------- pass C (fp16 mma): O = (mask o QK^T) V + lamq o (Q KV) -------
// smem: dpw f32[136] | Qs[128][72] | Ks/Vs[128][72] | KVs[64][72] | Ss[128][136]
__global__ __launch_bounds__(256) void attn_h_k(
    const __half* __restrict__ QKV, const float* __restrict__ KVi,
    __half* __restrict__ Og)
{
    extern __shared__ char smc[];
    float* dpw = (float*)smc;
    __half* Qs = (__half*)(smc + 544);
    __half* Ks = Qs + 128 * 72;
    __half* KVs = Ks + 128 * 72;
    __half* Ss = KVs + 64 * 72;
    const uint32_t smb = (uint32_t)__cvta_generic_to_shared(smc);
    const uint32_t qB = smb + 544;
    const uint32_t kB = qB + 128 * 72 * 2;
    const uint32_t kvB = kB + 128 * 72 * 2;
    const uint32_t sB = kvB + 64 * 72 * 2;

    const int c = blockIdx.x, bh = blockIdx.y;
    const int b = bh >> 4, h = bh & 15;
    const int tid = threadIdx.x;
    const int lane = tid & 31, wid = tid >> 5;
    const int gid = lane >> 2, tg = lane & 3;
    const int arow = lane & 15;
    const int acol = (lane >> 4) << 3;
    const int brow = lane & 7;
    const int bcol = ((lane >> 3) & 1) << 3;
    const float s = head_slope(h);
    if (tid < 129) dpw[tid] = __expf(-s * (float)tid);

    const size_t rowbase = (size_t)b * 8192 + (size_t)c * 128;
    const int colbase = h * 64;

    // Q and K rows (natural [i][d]); KV fp32 -> half [d][e]
#pragma unroll
    for (int i = 0; i < 4; ++i) {
        const int idx = tid + (i << 8);
        const int r = idx >> 3, ch = (idx & 7) << 3;
        const size_t g = (rowbase + r) * QKVN + colbase + ch;
        *(uint4*)(Qs + r * 72 + ch) = *(const uint4*)(QKV + g);
        *(uint4*)(Ks + r * 72 + ch) = *(const uint4*)(QKV + g + 1024);
    }
    {
        const float* kvsrc = KVi + ((size_t)bh * NCH + c) * 4096;
#pragma unroll
        for (int i = 0; i < 8; ++i) {
            const int idx = tid + (i << 8);          // float2 slots: 2048
            const int d = idx >> 5, e2 = (idx & 31) << 1;
            float2 f = *(const float2*)(kvsrc + d * 64 + e2);
            *(__half2*)(KVs + d * 72 + e2) = __floats2half2_rn(f.x, f.y);
        }
    }
    __syncthreads();

    // merged phase 1+3: S = Q K^T (64x32), oc = Q KV (64x16); k = d over 64
    const int wmS = (wid >> 2) * 64, wnS = (wid & 3) * 32;
    const int wnO = (wid & 3) * 16;
    float sc[4][4][4];
    float oc[4][2][4];
#pragma unroll
    for (int i = 0; i < 4; i++) {
#pragma unroll
        for (int j = 0; j < 4; j++)
#pragma unroll
            for (int q = 0; q < 4; q++) sc[i][j][q] = 0.f;
#pragma unroll
        for (int j = 0; j < 2; j++)
#pragma unroll
            for (int q = 0; q < 4; q++) oc[i][j][q] = 0.f;
    }

#pragma unroll
    for (int ks = 0; ks < 4; ++ks) {
        const int k0 = ks << 4;
        uint32_t af[4][4], bf[4][2], bk[2][2];
#pragma unroll
        for (int mt = 0; mt < 4; mt++)
            LDSM_X4(af[mt], qB + (uint32_t)((wmS + mt * 16 + arow) * 72 + k0 + acol) * 2u);
#pragma unroll
        for (int nt = 0; nt < 4; nt++)       // B = Ks [n=j][k=d], non-trans
            LDSM_X2(bf[nt], kB + (uint32_t)((wnS + nt * 8 + brow) * 72 + k0 + bcol) * 2u);
        const int kvr = k0 + (lane & 7) + (((lane >> 3) & 1) << 3);
#pragma unroll
        for (int nt = 0; nt < 2; nt++)       // B = KVs [k=d][n=e], trans
            LDSM_X2T(bk[nt], kvB + (uint32_t)(kvr * 72 + wnO + nt * 8) * 2u);
#pragma unroll
        for (int mt = 0; mt < 4; mt++) {
#pragma unroll
            for (int nt = 0; nt < 4; nt++)
                MMA_F16(sc[mt][nt], af[mt][0], af[mt][1], af[mt][2], af[mt][3],
                        bf[nt][0], bf[nt][1]);
#pragma unroll
            for (int nt = 0; nt < 2; nt++)
                MMA_F16(oc[mt][nt], af[mt][0], af[mt][1], af[mt][2], af[mt][3],
                        bk[nt][0], bk[nt][1]);
        }
    }

    // mask + decay, write S to smem (half)
#pragma unroll
    for (int mt = 0; mt < 4; mt++) {
#pragma unroll
        for (int nt = 0; nt < 4; nt++) {
            const int i0 = wmS + mt * 16 + gid;
            const int j0 = wnS + nt * 8 + 2 * tg;
            const int d00 = i0 - j0;
            float v0 = (d00 >= 0) ? sc[mt][nt][0] * dpw[d00] : 0.f;
            float v1 = (d00 >= 1) ? sc[mt][nt][1] * dpw[d00 - 1] : 0.f;
            float v2 = (d00 >= -8) ? sc[mt][nt][2] * dpw[d00 + 8] : 0.f;
            float v3 = (d00 >= -7) ? sc[mt][nt][3] * dpw[d00 + 7] : 0.f;
            *(__half2*)(Ss + i0 * 136 + j0) = __floats2half2_rn(v0, v1);
            *(__half2*)(Ss + (i0 + 8) * 136 + j0) = __floats2half2_rn(v2, v3);
        }
    }

    // scale oc by lamq[i] = dpw[i+1]
#pragma unroll
    for (int mt = 0; mt < 4; mt++) {
        const int i0 = wmS + mt * 16 + gid;
        const float l0 = dpw[i0 + 1], l1 = dpw[i0 + 9];
#pragma unroll
        for (int nt = 0; nt < 2; nt++) {
            oc[mt][nt][0] *= l0; oc[mt][nt][1] *= l0;
            oc[mt][nt][2] *= l1; oc[mt][nt][3] *= l1;
        }
    }

    __syncthreads();      // S written; K/KV reads done

    // V rows into Ks region (natural [j][e])
#pragma unroll
    for (int i = 0; i < 4; ++i) {
        const int idx = tid + (i << 8);
        const int r = idx >> 3, ch = (idx & 7) << 3;
        *(uint4*)(Ks + r * 72 + ch) =
            *(const uint4*)(QKV + (rowbase + r) * QKVN + 2048 + colbase + ch);
    }
    __syncthreads();

    // phase 2: oc += S @ V.  A = Ss [i][j] x4; B = Vs [k=j][n=e] trans-x2.
#pragma unroll
    for (int ks = 0; ks < 8; ++ks) {
        const int k0 = ks << 4;
        uint32_t af[4][4], bf[2][2];
#pragma unroll
        for (int mt = 0; mt < 4; mt++)
            LDSM_X4(af[mt], sB + (uint32_t)((wmS + mt * 16 + arow) * 136 + k0 + acol) * 2u);
        const int vkr = k0 + (lane & 7) + (((lane >> 3) & 1) << 3);
#pragma unroll
        for (int nt = 0; nt < 2; nt++)
            LDSM_X2T(bf[nt], kB + (uint32_t)(vkr * 72 + wnO + nt * 8) * 2u);
#pragma unroll
        for (int mt = 0; mt < 4; mt++)
#pragma unroll
            for (int nt = 0; nt < 2; nt++)
                MMA_F16(oc[mt][nt], af[mt][0], af[mt][1], af[mt][2], af[mt][3],
                        bf[nt][0], bf[nt][1]);
    }

    // write O (half)
#pragma unroll
    for (int mt = 0; mt < 4; mt++) {
#pragma unroll
        for (int nt = 0; nt < 2; nt++) {
            const int i0 = wmS + mt * 16 + gid;
            const int e0 = wnO + nt * 8 + 2 * tg;
            *(__half2*)(Og + (rowbase + i0) * 1024 + colbase + e0) =
                __floats2half2_rn(oc[mt][nt][0], oc[mt][nt][1]);
            *(__half2*)(Og + (rowbase + i0 + 8) * 1024 + colbase + e0) =
                __floats2half2_rn(oc[mt][nt][2], oc[mt][nt][3]);
        }
    }
}

// ------------- LayerNorm * gate (half in, half out) -------------------------
__global__ __launch_bounds__(256) void ln_gate_h(
    const __half* __restrict__ O, const __half* __restrict__ G,
    const float* __restrict__ gamma, const float* __restrict__ beta,
    __half* __restrict__ OLN)
{
    __shared__ float red[2][8];
    const int row = blockIdx.x, tid = threadIdx.x;
    const size_t base = (size_t)row * 1024 + (tid << 2);
    float2 a = __half22float2(*(const __half2*)(O + base));
    float2 bb = __half22float2(*(const __half2*)(O + base + 2));
    float sum = a.x + a.y + bb.x + bb.y;
    float sq = a.x * a.x + a.y * a.y + bb.x * bb.x + bb.y * bb.y;
#pragma unroll
    for (int o = 16; o > 0; o >>= 1) {
        sum += __shfl_xor_sync(0xffffffff, sum, o);
        sq += __shfl_xor_sync(0xffffffff, sq, o);
    }
    if ((tid & 31) == 0) { red[0][tid >> 5] = sum; red[1][tid >> 5] = sq; }
    __syncthreads();
    float ts = 0.f, tq = 0.f;
#pragma unroll
    for (int w = 0; w < 8; w++) { ts += red[0][w]; tq += red[1][w]; }
    const float mu = ts * (1.f / 1024.f);
    const float var = tq * (1.f / 1024.f) - mu * mu;
    const float rstd = rsqrtf(var + 1e-5f);

    float4 g4 = *(const float4*)(gamma + (tid << 2));
    float4 b4 = *(const float4*)(beta + (tid << 2));
    float2 gt0 = __half22float2(*(const __half2*)(G + base));
    float2 gt1 = __half22float2(*(const __half2*)(G + base + 2));
    float o0 = ((a.x - mu) * rstd * g4.x + b4.x) * gt0.x;
    float o1 = ((a.y - mu) * rstd * g4.y + b4.y) * gt0.y;
    float o2 = ((bb.x - mu) * rstd * g4.z + b4.z) * gt1.x;
    float o3 = ((bb.y - mu) * rstd * g4.w + b4.w) * gt1.y;
    *(__half2*)(OLN + base) = __floats2half2_rn(o0, o1);
    *(__half2*)(OLN + base + 2) = __floats2half2_rn(o2, o3);
}

// ---------------------------------------------------------------------------
extern "C" void kernel_launch(void* const* d_in, const int* in_sizes, int n_in,
                              void* d_out, int out_size)
{
    const float* x     = (const float*)d_in[0];
    const float* Wq    = (const float*)d_in[1];
    const float* Wk    = (const float*)d_in[2];
    const float* Wv    = (const float*)d_in[3];
    const float* Wo    = (const float*)d_in[4];
    const float* gamma = (const float*)d_in[5];
    const float* beta  = (const float*)d_in[6];
    const float* Wg1   = (const float*)d_in[7];
    const float* Wg2   = (const float*)d_in[8];
    float* out = (float*)d_out;

    void *pX, *pWqkv, *pWo, *pWg1, *pWg2, *pQKV, *pG1, *pGATE, *pO, *pOLN, *pM, *pKV;
    cudaGetSymbolAddress(&pX, hX);
    cudaGetSymbolAddress(&pWqkv, hWqkv);
    cudaGetSymbolAddress(&pWo, hWo);
    cudaGetSymbolAddress(&pWg1, hWg1);
    cudaGetSymbolAddress(&pWg2, hWg2);
    cudaGetSymbolAddress(&pQKV, hQKV);
    cudaGetSymbolAddress(&pG1, hG1);
    cudaGetSymbolAddress(&pGATE, hGATE);
    cudaGetSymbolAddress(&pO, hO);
    cudaGetSymbolAddress(&pOLN, hOLN);
    cudaGetSymbolAddress(&pM, gM);
    cudaGetSymbolAddress(&pKV, gKV);
    __half* X = (__half*)pX;       __half* Wqkv = (__half*)pWqkv;
    __half* WoH = (__half*)pWo;    __half* Wg1H = (__half*)pWg1;
    __half* Wg2H = (__half*)pWg2;  __half* QKV = (__half*)pQKV;
    __half* G1 = (__half*)pG1;     __half* GATE = (__half*)pGATE;
    __half* O = (__half*)pO;       __half* OLN = (__half*)pOLN;
    float* Mb = (float*)pM;        float* KVb = (float*)pKV;

    // smem sizes
    const int smG128 = 3 * (128 * 72 + 64 * 136) * 2;   // 107520
    const int smG64  = 3 * (128 * 72 + 64 * 72) * 2;    //  82944
    const int smAttn = 544 + (128 * 72 + 128 * 72 + 64 * 72 + 128 * 136) * 2;
    const int smCkv  = 544 + (128 * 72 + 128 * 72) * 2;
    cudaFuncSetAttribute(tgemm_h<1, 128, true>,
                         cudaFuncAttributeMaxDynamicSharedMemorySize, smG128);
    cudaFuncSetAttribute(tgemm_h<2, 128, true>,
                         cudaFuncAttributeMaxDynamicSharedMemorySize, smG128);
    cudaFuncSetAttribute(tgemm_h<0, 128, false>,
                         cudaFuncAttributeMaxDynamicSharedMemorySize, smG128);
    cudaFuncSetAttribute(tgemm_h<0, 64, true>,
                         cudaFuncAttributeMaxDynamicSharedMemorySize, smG64);
    cudaFuncSetAttribute(attn_h_k,
                         cudaFuncAttributeMaxDynamicSharedMemorySize, smAttn);
    cudaFuncSetAttribute(ckv_h_k,
                         cudaFuncAttributeMaxDynamicSharedMemorySize, smCkv);

    // ---- prep: convert to fp16 ----
    cvt_half_k<<<MDIM * EDIM / 1024, 256>>>((const float4*)x, X);
    cvt_qkv_k<<<1024, 256>>>(Wq, Wqkv, 0);
    cvt_qkv_k<<<1024, 256>>>(Wk, Wqkv, 1024);
    cvt_qkv_k<<<1024, 256>>>(Wv, Wqkv, 2048);
    cvt_half_k<<<EDIM * EDIM / 1024, 256>>>((const float4*)Wo, WoH);
    cvt_half_k<<<EDIM * DH / 1024, 256>>>((const float4*)Wg1, Wg1H);
    cvt_half_k<<<EDIM * DH / 1024, 256>>>((const float4*)Wg2, Wg2H);

    dim3 tB(256);

    // fused QKV projection: [M,3072] = silu(X @ Wqkv)
    tgemm_h<1, 128, true><<<dim3(QKVN / 128, MDIM / 128), tB, smG128>>>(
        X, Wqkv, QKV, MDIM, QKVN, EDIM);

    // gate path
    tgemm_h<0, 64, true><<<dim3(1, MDIM / 128), tB, smG64>>>(
        X, Wg1H, G1, MDIM, DH, EDIM);
    tgemm_h<2, 128, true><<<dim3(EDIM / 128, MDIM / 128), tB, smG128>>>(
        G1, Wg2H, GATE, MDIM, EDIM, DH);

    // attention
    ckv_h_k<<<dim3(NCH, BHN), tB, smCkv>>>(QKV, Mb);
    kv_scan_k<<<dim3(16, BHN), tB>>>(Mb, KVb);
    attn_h_k<<<dim3(NCH, BHN), tB, smAttn>>>(QKV, KVb, O);

    // layernorm * gate, final projection (fp32 out)
    ln_gate_h<<<MDIM, tB>>>(O, GATE, gamma, beta, OLN);
    tgemm_h<0, 128, false><<<dim3(EDIM / 128, MDIM / 128), tB, smG128>>>(
        OLN, WoH, out, MDIM, EDIM, EDIM);
}

// round 12
// speedup vs baseline: 5.9344x; 1.0193x over previous
#include <cuda_runtime.h>
#include <cuda_fp16.h>
#include <math.h>
#include <stdint.h>

// Problem constants
#define MDIM 16384          // B*N = 2*8192 rows
#define EDIM 1024           // embed
#define DH   64             // head dim
#define NCH  64             // chunks per sequence (8192/128)
#define BHN  32             // B*H
#define QKVN 3072           // fused projection width

// ---------------- scratch (device globals) ----------------------------------
__device__ __half hX[MDIM * EDIM];
__device__ __half hWqkv[EDIM * QKVN];     // [k][n] concat Wq|Wk|Wv
__device__ __half hWo[EDIM * EDIM];       // [k][n]
__device__ __half hWg1[EDIM * DH];        // [k][n]
__device__ __half hWg2[DH * EDIM];        // [k][n]
__device__ __half hQKV[MDIM * QKVN];      // fused silu(xW) outputs
__device__ __half hG1[MDIM * DH];
__device__ __half hGATE[MDIM * EDIM];
__device__ __half hO[MDIM * EDIM];
__device__ __half hOLN[MDIM * EDIM];
__device__ float gM[BHN * NCH * DH * DH];
__device__ float gKV[BHN * NCH * DH * DH];

// ---------------- streams/events for graph fork-join (created at load) ------
static cudaStream_t g_s1 = nullptr;
static cudaEvent_t g_evFork = nullptr, g_evW = nullptr, g_evX = nullptr,
                   g_evGate = nullptr;
namespace {
struct StreamInit {
    StreamInit() {
        cudaStreamCreateWithFlags(&g_s1, cudaStreamNonBlocking);
        cudaEventCreateWithFlags(&g_evFork, cudaEventDisableTiming);
        cudaEventCreateWithFlags(&g_evW, cudaEventDisableTiming);
        cudaEventCreateWithFlags(&g_evX, cudaEventDisableTiming);
        cudaEventCreateWithFlags(&g_evGate, cudaEventDisableTiming);
    }
};
StreamInit g_stream_init;
}

__device__ __forceinline__ float head_slope(int h) {
    return exp2f(-0.5f * (float)(h + 1)) * 1.00001f;
}

template <int EPI>
__device__ __forceinline__ float epilogue(float v) {
    if (EPI == 1) {                       // silu (fast-math)
        const float e = __expf(-v);
        return __fdividef(v, 1.f + e);
    }
    if (EPI == 2) {                       // sigmoid (fast-math)
        const float e = __expf(-v);
        return __fdividef(1.f, 1.f + e);
    }
    return v;
}

#define MMA_F16(acc, a0, a1, a2, a3, b0, b1) \
    asm volatile( \
        "mma.sync.aligned.m16n8k16.row.col.f32.f16.f16.f32 " \
        "{%0,%1,%2,%3}, {%4,%5,%6,%7}, {%8,%9}, {%0,%1,%2,%3};\n" \
        : "+f"((acc)[0]), "+f"((acc)[1]), "+f"((acc)[2]), "+f"((acc)[3]) \
        : "r"(a0), "r"(a1), "r"(a2), "r"(a3), "r"(b0), "r"(b1))

#define LDSM_X4(r, addr) \
    asm volatile("ldmatrix.sync.aligned.m8n8.x4.shared.b16 {%0,%1,%2,%3}, [%4];" \
        : "=r"((r)[0]), "=r"((r)[1]), "=r"((r)[2]), "=r"((r)[3]) : "r"(addr))
#define LDSM_X2(r, addr) \
    asm volatile("ldmatrix.sync.aligned.m8n8.x2.shared.b16 {%0,%1}, [%2];" \
        : "=r"((r)[0]), "=r"((r)[1]) : "r"(addr))
#define LDSM_X4T(r, addr) \
    asm volatile("ldmatrix.sync.aligned.m8n8.x4.trans.shared.b16 {%0,%1,%2,%3}, [%4];" \
        : "=r"((r)[0]), "=r"((r)[1]), "=r"((r)[2]), "=r"((r)[3]) : "r"(addr))
#define LDSM_X2T(r, addr) \
    asm volatile("ldmatrix.sync.aligned.m8n8.x2.trans.shared.b16 {%0,%1}, [%2];" \
        : "=r"((r)[0]), "=r"((r)[1]) : "r"(addr))

__device__ __forceinline__ void cpa_wait(int keep) {
    if (keep <= 0)      asm volatile("cp.async.wait_group 0;" ::);
    else                asm volatile("cp.async.wait_group 1;" ::);
}

// =================== FP16 mma.sync GEMM =====================================
// C = epi(A @ B). A[M,K] half row-major, B[K,N] half row-major.
// 128 x BN_ x 64 tile, 256 thr (8 warps 2x4), warp tile 64 x (BN_/4),
// A via ldmatrix.x4, B via ldmatrix.x2.trans. 3-stage cp.async.
template <int EPI, int BN_, bool HOUT>
__global__ __launch_bounds__(256, 2) void tgemm_h(
    const __half* __restrict__ A, const __half* __restrict__ B,
    void* __restrict__ Cv, int M, int N, int K)
{
    constexpr int AST = 72;                 // A row stride (halves), 64 + pad
    constexpr int BST = BN_ + 8;            // B row stride (halves)
    constexpr int SA_H = 128 * AST;
    constexpr int SB_H = 64 * BST;
    constexpr int STAGE_H = SA_H + SB_H;
    constexpr int CPR = BN_ / 8;            // 16B chunks per B row
    constexpr int BITER = (64 * CPR) / 256;
    constexpr int NT = BN_ / 32;

    extern __shared__ __half smh[];
    const int tid = threadIdx.x;
    const int lane = tid & 31, wid = tid >> 5;
    const int gid = lane >> 2, tg = lane & 3;
    const int wm = (wid >> 2) * 64;
    const int wn = (wid & 3) * (BN_ / 4);
    const int bm = blockIdx.y << 7;
    const int bn = blockIdx.x * BN_;
    const uint32_t smu = (uint32_t)__cvta_generic_to_shared(smh);
    const int KT = K >> 6;                  // 64 halves per k-tile

    const int arow = lane & 15;
    const int acol = (lane >> 4) << 3;      // 0 or 8 halves

    auto fill = [&](int kt) {
        const uint32_t sa = smu + (uint32_t)((kt % 3) * STAGE_H) * 2u;
        const uint32_t sb = sa + (uint32_t)SA_H * 2u;
#pragma unroll
        for (int i = 0; i < 4; i++) {
            const int idx = tid + (i << 8);
            const int row = idx >> 3, ch = idx & 7;
            const __half* src = A + (size_t)(bm + row) * K + (kt << 6) + (ch << 3);
            asm volatile("cp.async.cg.shared.global [%0], [%1], 16;"
                         :: "r"(sa + (uint32_t)(row * AST + (ch << 3)) * 2u), "l"(src));
        }
#pragma unroll
        for (int i = 0; i < BITER; i++) {
            const int idx = tid + (i << 8);
            const int row = idx / CPR, ch = idx % CPR;
            const __half* src = B + (size_t)((kt << 6) + row) * N + bn + (ch << 3);
            asm volatile("cp.async.cg.shared.global [%0], [%1], 16;"
                         :: "r"(sb + (uint32_t)(row * BST + (ch << 3)) * 2u), "l"(src));
        }
        asm volatile("cp.async.commit_group;");
    };

    float acc[4][NT][4];
#pragma unroll
    for (int i = 0; i < 4; i++)
#pragma unroll
        for (int j = 0; j < NT; j++)
#pragma unroll
            for (int q = 0; q < 4; q++) acc[i][j][q] = 0.f;

    fill(0);
    if (KT > 1) fill(1);

    for (int kt = 0; kt < KT; ++kt) {
        cpa_wait((kt + 1 < KT) ? 1 : 0);
        __syncthreads();
        if (kt + 2 < KT) fill(kt + 2);

        const uint32_t sa = smu + (uint32_t)((kt % 3) * STAGE_H) * 2u;
        const uint32_t sb = sa + (uint32_t)SA_H * 2u;
#pragma unroll
        for (int ks = 0; ks < 4; ++ks) {
            const int k0 = ks << 4;
            uint32_t af[4][4], bf[NT][2];
#pragma unroll
            for (int mt = 0; mt < 4; mt++)
                LDSM_X4(af[mt], sa + (uint32_t)((wm + mt * 16 + arow) * AST + k0 + acol) * 2u);
            // B rows are k; trans load from [k][n]
            const int krow = k0 + (lane & 7) + ((lane >> 3) & 1) * 8;
#pragma unroll
            for (int nt = 0; nt < NT; nt++)
                LDSM_X2T(bf[nt], sb + (uint32_t)(krow * BST + wn + nt * 8) * 2u);
#pragma unroll
            for (int mt = 0; mt < 4; mt++)
#pragma unroll
                for (int nt = 0; nt < NT; nt++)
                    MMA_F16(acc[mt][nt], af[mt][0], af[mt][1], af[mt][2], af[mt][3],
                            bf[nt][0], bf[nt][1]);
        }
    }

#pragma unroll
    for (int mt = 0; mt < 4; mt++) {
#pragma unroll
        for (int nt = 0; nt < NT; nt++) {
            const int r0 = bm + wm + mt * 16 + gid;
            const int c = bn + wn + nt * 8 + 2 * tg;
            float e0 = epilogue<EPI>(acc[mt][nt][0]);
            float e1 = epilogue<EPI>(acc[mt][nt][1]);
            float e2 = epilogue<EPI>(acc[mt][nt][2]);
            float e3 = epilogue<EPI>(acc[mt][nt][3]);
            if (HOUT) {
                __half* C = (__half*)Cv;
                *(__half2*)(C + (size_t)r0 * N + c) = __floats2half2_rn(e0, e1);
                *(__half2*)(C + (size_t)(r0 + 8) * N + c) = __floats2half2_rn(e2, e3);
            } else {
                float* C = (float*)Cv;
                *(float2*)(C + (size_t)r0 * N + c) = make_float2(e0, e1);
                *(float2*)(C + (size_t)(r0 + 8) * N + c) = make_float2(e2, e3);
            }
        }
    }
}

// ---------------- prep: fp32 -> fp16 converts --------------------------------
__global__ __launch_bounds__(256) void cvt_half_k(
    const float4* __restrict__ in, __half* __restrict__ out)
{
    const int i = blockIdx.x * 256 + threadIdx.x;
    float4 v = in[i];
    __half2* o = (__half2*)(out + (size_t)i * 4);
    o[0] = __floats2half2_rn(v.x, v.y);
    o[1] = __floats2half2_rn(v.z, v.w);
}

// W [1024][1024] fp32 -> dst[k][off + n] within [1024][3072] half
__global__ __launch_bounds__(256) void cvt_qkv_k(
    const float* __restrict__ src, __half* __restrict__ dst, int off)
{
    const int i4 = blockIdx.x * 256 + threadIdx.x;     // float4 index
    const int k = i4 >> 8, n4 = (i4 & 255) << 2;
    float4 v = *(const float4*)(src + (size_t)k * 1024 + n4);
    __half2* o = (__half2*)(dst + (size_t)k * QKVN + off + n4);
    o[0] = __floats2half2_rn(v.x, v.y);
    o[1] = __floats2half2_rn(v.z, v.w);
}

// ------------- pass A (fp16 mma): M = K^T diag(lamk) V  [64x64] -------------
// smem: dpw f32[136] | Ks[128][72] h | Vs[128][72] h  (natural [j][feat])
__global__ __launch_bounds__(256) void ckv_h_k(
    const __half* __restrict__ QKV, float* __restrict__ Mo)
{
    extern __shared__ char smc[];
    float* dpw = (float*)smc;
    __half* Ks = (__half*)(smc + 544);
    __half* Vs = Ks + 128 * 72;
    const uint32_t smb = (uint32_t)__cvta_generic_to_shared(smc);
    const uint32_t kB = smb + 544;
    const uint32_t vB = kB + 128 * 72 * 2;

    const int c = blockIdx.x, bh = blockIdx.y;
    const int b = bh >> 4, h = bh & 15;
    const int tid = threadIdx.x;
    const int lane = tid & 31, wid = tid >> 5;
    const int gid = lane >> 2, tg = lane & 3;
    const float s = head_slope(h);
    if (tid < 129) dpw[tid] = __expf(-s * (float)tid);
    __syncthreads();

    const size_t rowbase = (size_t)b * 8192 + (size_t)c * 128;
    const int colbase = h * 64;

    // K scaled by lamk (fp32 math, rn to half); V plain copy
#pragma unroll
    for (int i = 0; i < 16; ++i) {
        const int idx = tid + (i << 8);            // half2 slots: 4096
        const int j = idx >> 5, c2 = (idx & 31) << 1;
        const __half2 kv2 = *(const __half2*)(QKV + (rowbase + j) * QKVN + 1024 + colbase + c2);
        const float lk = dpw[127 - j];
        float2 f = __half22float2(kv2);
        *(__half2*)(Ks + j * 72 + c2) = __floats2half2_rn(f.x * lk, f.y * lk);
    }
#pragma unroll
    for (int i = 0; i < 4; ++i) {
        const int idx = tid + (i << 8);            // 16B chunks: 1024
        const int j = idx >> 3, ch = (idx & 7) << 3;
        *(uint4*)(Vs + j * 72 + ch) =
            *(const uint4*)(QKV + (rowbase + j) * QKVN + 2048 + colbase + ch);
    }
    __syncthreads();

    // m=d (64), n=e (64), k=j (128). A=K^T via trans-x4, B=V^T via trans-x2.
    const int wm = (wid >> 2) * 32;
    const int wn = (wid & 3) * 16;
    float acc[2][2][4];
#pragma unroll
    for (int i = 0; i < 2; i++)
#pragma unroll
        for (int j = 0; j < 2; j++)
#pragma unroll
            for (int q = 0; q < 4; q++) acc[i][j][q] = 0.f;

#pragma unroll
    for (int ks = 0; ks < 8; ++ks) {
        const int k0 = ks << 4;
        uint32_t af[2][4], bf[2][2];
        const int akr = k0 + ((lane >> 4) << 3) + (lane & 7);
        const int amc = ((lane >> 3) & 1) << 3;
        const int bkr = k0 + (lane & 7) + (((lane >> 3) & 1) << 3);
#pragma unroll
        for (int mt = 0; mt < 2; mt++)
            LDSM_X4T(af[mt], kB + (uint32_t)(akr * 72 + wm + mt * 16 + amc) * 2u);
#pragma unroll
        for (int nt = 0; nt < 2; nt++)
            LDSM_X2T(bf[nt], vB + (uint32_t)(bkr * 72 + wn + nt * 8) * 2u);
#pragma unroll
        for (int mt = 0; mt < 2; mt++)
#pragma unroll
            for (int nt = 0; nt < 2; nt++)
                MMA_F16(acc[mt][nt], af[mt][0], af[mt][1], af[mt][2], af[mt][3],
                        bf[nt][0], bf[nt][1]);
    }

    float* out = Mo + ((size_t)bh * NCH + c) * 4096;
#pragma unroll
    for (int mt = 0; mt < 2; mt++) {
#pragma unroll
        for (int nt = 0; nt < 2; nt++) {
            const int i0 = wm + mt * 16 + gid;
            const int j0 = wn + nt * 8 + 2 * tg;
            *(float2*)(out + i0 * 64 + j0) = make_float2(acc[mt][nt][0], acc[mt][nt][1]);
            *(float2*)(out + (i0 + 8) * 64 + j0) = make_float2(acc[mt][nt][2], acc[mt][nt][3]);
        }
    }
}

// ------------- pass B: decayed prefix scan of M over chunks -----------------
__global__ __launch_bounds__(256) void kv_scan_k(
    const float* __restrict__ Mi, float* __restrict__ KVo)
{
    const int bh = blockIdx.y;
    const int elem = blockIdx.x * 256 + threadIdx.x;
    const int h = bh & 15;
    const float s = head_slope(h);
    const float lamc = __expf(-s * 128.f);

    float acc = 0.f;
    const size_t base = (size_t)bh * NCH * 4096 + elem;
    for (int c = 0; c < NCH; ++c) {
        const size_t idx = base + (size_t)c * 4096;
        KVo[idx] = acc;
        acc = fmaf(lamc, acc, Mi[idx]);
    }
}

// ------------- pass C (fp16 mma): O = (mask o QK^T) V + lamq o (Q KV) -------
// smem: dpw f32[136] | Qs[128][72] | Ks/Vs[128][72] | KVs[64][72] | Ss[128][136]
__global__ __launch_bounds__(256) void attn_h_k(
    const __half* __restrict__ QKV, const float* __restrict__ KVi,
    __half* __restrict__ Og)
{
    extern __shared__ char smc[];
    float* dpw = (float*)smc;
    __half* Qs = (__half*)(smc + 544);
    __half* Ks = Qs + 128 * 72;
    __half* KVs = Ks + 128 * 72;
    __half* Ss = KVs + 64 * 72;
    const uint32_t smb = (uint32_t)__cvta_generic_to_shared(smc);
    const uint32_t qB = smb + 544;
    const uint32_t kB = qB + 128 * 72 * 2;
    const uint32_t kvB = kB + 128 * 72 * 2;
    const uint32_t sB = kvB + 64 * 72 * 2;

    const int c = blockIdx.x, bh = blockIdx.y;
    const int b = bh >> 4, h = bh & 15;
    const int tid = threadIdx.x;
    const int lane = tid & 31, wid = tid >> 5;
    const int gid = lane >> 2, tg = lane & 3;
    const int arow = lane & 15;
    const int acol = (lane >> 4) << 3;
    const int brow = lane & 7;
    const int bcol = ((lane >> 3) & 1) << 3;
    const float s = head_slope(h);
    if (tid < 129) dpw[tid] = __expf(-s * (float)tid);

    const size_t rowbase = (size_t)b * 8192 + (size_t)c * 128;
    const int colbase = h * 64;

    // Q and K rows (natural [i][d]); KV fp32 -> half [d][e]
#pragma unroll
    for (int i = 0; i < 4; ++i) {
        const int idx = tid + (i << 8);
        const int r = idx >> 3, ch = (idx & 7) << 3;
        const size_t g = (rowbase + r) * QKVN + colbase + ch;
        *(uint4*)(Qs + r * 72 + ch) = *(const uint4*)(QKV + g);
        *(uint4*)(Ks + r * 72 + ch) = *(const uint4*)(QKV + g + 1024);
    }
    {
        const float* kvsrc = KVi + ((size_t)bh * NCH + c) * 4096;
#pragma unroll
        for (int i = 0; i < 8; ++i) {
            const int idx = tid + (i << 8);          // float2 slots: 2048
            const int d = idx >> 5, e2 = (idx & 31) << 1;
            float2 f = *(const float2*)(kvsrc + d * 64 + e2);
            *(__half2*)(KVs + d * 72 + e2) = __floats2half2_rn(f.x, f.y);
        }
    }
    __syncthreads();

    // merged phase 1+3: S = Q K^T (64x32), oc = Q KV (64x16); k = d over 64
    const int wmS = (wid >> 2) * 64, wnS = (wid & 3) * 32;
    const int wnO = (wid & 3) * 16;
    float sc[4][4][4];
    float oc[4][2][4];
#pragma unroll
    for (int i = 0; i < 4; i++) {
#pragma unroll
        for (int j = 0; j < 4; j++)
#pragma unroll
            for (int q = 0; q < 4; q++) sc[i][j][q] = 0.f;
#pragma unroll
        for (int j = 0; j < 2; j++)
#pragma unroll
            for (int q = 0; q < 4; q++) oc[i][j][q] = 0.f;
    }

#pragma unroll
    for (int ks = 0; ks < 4; ++ks) {
        const int k0 = ks << 4;
        uint32_t af[4][4], bf[4][2], bk[2][2];
#pragma unroll
        for (int mt = 0; mt < 4; mt++)
            LDSM_X4(af[mt], qB + (uint32_t)((wmS + mt * 16 + arow) * 72 + k0 + acol) * 2u);
#pragma unroll
        for (int nt = 0; nt < 4; nt++)       // B = Ks [n=j][k=d], non-trans
            LDSM_X2(bf[nt], kB + (uint32_t)((wnS + nt * 8 + brow) * 72 + k0 + bcol) * 2u);
        const int kvr = k0 + (lane & 7) + (((lane >> 3) & 1) << 3);
#pragma unroll
        for (int nt = 0; nt < 2; nt++)       // B = KVs [k=d][n=e], trans
            LDSM_X2T(bk[nt], kvB + (uint32_t)(kvr * 72 + wnO + nt * 8) * 2u);
#pragma unroll
        for (int mt = 0; mt < 4; mt++) {
#pragma unroll
            for (int nt = 0; nt < 4; nt++)
                MMA_F16(sc[mt][nt], af[mt][0], af[mt][1], af[mt][2], af[mt][3],
                        bf[nt][0], bf[nt][1]);
#pragma unroll
            for (int nt = 0; nt < 2; nt++)
                MMA_F16(oc[mt][nt], af[mt][0], af[mt][1], af[mt][2], af[mt][3],
                        bk[nt][0], bk[nt][1]);
        }
    }

    // mask + decay, write S to smem (half)
#pragma unroll
    for (int mt = 0; mt < 4; mt++) {
#pragma unroll
        for (int nt = 0; nt < 4; nt++) {
            const int i0 = wmS + mt * 16 + gid;
            const int j0 = wnS + nt * 8 + 2 * tg;
            const int d00 = i0 - j0;
            float v0 = (d00 >= 0) ? sc[mt][nt][0] * dpw[d00] : 0.f;
            float v1 = (d00 >= 1) ? sc[mt][nt][1] * dpw[d00 - 1] : 0.f;
            float v2 = (d00 >= -8) ? sc[mt][nt][2] * dpw[d00 + 8] : 0.f;
            float v3 = (d00 >= -7) ? sc[mt][nt][3] * dpw[d00 + 7] : 0.f;
            *(__half2*)(Ss + i0 * 136 + j0) = __floats2half2_rn(v0, v1);
            *(__half2*)(Ss + (i0 + 8) * 136 + j0) = __floats2half2_rn(v2, v3);
        }
    }

    // scale oc by lamq[i] = dpw[i+1]
#pragma unroll
    for (int mt = 0; mt < 4; mt++) {
        const int i0 = wmS + mt * 16 + gid;
        const float l0 = dpw[i0 + 1], l1 = dpw[i0 + 9];
#pragma unroll
        for (int nt = 0; nt < 2; nt++) {
            oc[mt][nt][0] *= l0; oc[mt][nt][1] *= l0;
            oc[mt][nt][2] *= l1; oc[mt][nt][3] *= l1;
        }
    }

    __syncthreads();      // S written; K/KV reads done

    // V rows into Ks region (natural [j][e])
#pragma unroll
    for (int i = 0; i < 4; ++i) {
        const int idx = tid + (i << 8);
        const int r = idx >> 3, ch = (idx & 7) << 3;
        *(uint4*)(Ks + r * 72 + ch) =
            *(const uint4*)(QKV + (rowbase + r) * QKVN + 2048 + colbase + ch);
    }
    __syncthreads();

    // phase 2: oc += S @ V.  A = Ss [i][j] x4; B = Vs [k=j][n=e] trans-x2.
#pragma unroll
    for (int ks = 0; ks < 8; ++ks) {
        const int k0 = ks << 4;
        uint32_t af[4][4], bf[2][2];
#pragma unroll
        for (int mt = 0; mt < 4; mt++)
            LDSM_X4(af[mt], sB + (uint32_t)((wmS + mt * 16 + arow) * 136 + k0 + acol) * 2u);
        const int vkr = k0 + (lane & 7) + (((lane >> 3) & 1) << 3);
#pragma unroll
        for (int nt = 0; nt < 2; nt++)
            LDSM_X2T(bf[nt], kB + (uint32_t)(vkr * 72 + wnO + nt * 8) * 2u);
#pragma unroll
        for (int mt = 0; mt < 4; mt++)
#pragma unroll
            for (int nt = 0; nt < 2; nt++)
                MMA_F16(oc[mt][nt], af[mt][0], af[mt][1], af[mt][2], af[mt][3],
                        bf[nt][0], bf[nt][1]);
    }

    // write O (half)
#pragma unroll
    for (int mt = 0; mt < 4; mt++) {
#pragma unroll
        for (int nt = 0; nt < 2; nt++) {
            const int i0 = wmS + mt * 16 + gid;
            const int e0 = wnO + nt * 8 + 2 * tg;
            *(__half2*)(Og + (rowbase + i0) * 1024 + colbase + e0) =
                __floats2half2_rn(oc[mt][nt][0], oc[mt][nt][1]);
            *(__half2*)(Og + (rowbase + i0 + 8) * 1024 + colbase + e0) =
                __floats2half2_rn(oc[mt][nt][2], oc[mt][nt][3]);
        }
    }
}

// ------------- LayerNorm * gate (half in, half out) -------------------------
__global__ __launch_bounds__(256) void ln_gate_h(
    const __half* __restrict__ O, const __half* __restrict__ G,
    const float* __restrict__ gamma, const float* __restrict__ beta,
    __half* __restrict__ OLN)
{
    __shared__ float red[2][8];
    const int row = blockIdx.x, tid = threadIdx.x;
    const size_t base = (size_t)row * 1024 + (tid << 2);
    float2 a = __half22float2(*(const __half2*)(O + base));
    float2 bb = __half22float2(*(const __half2*)(O + base + 2));
    float sum = a.x + a.y + bb.x + bb.y;
    float sq = a.x * a.x + a.y * a.y + bb.x * bb.x + bb.y * bb.y;
#pragma unroll
    for (int o = 16; o > 0; o >>= 1) {
        sum += __shfl_xor_sync(0xffffffff, sum, o);
        sq += __shfl_xor_sync(0xffffffff, sq, o);
    }
    if ((tid & 31) == 0) { red[0][tid >> 5] = sum; red[1][tid >> 5] = sq; }
    __syncthreads();
    float ts = 0.f, tq = 0.f;
#pragma unroll
    for (int w = 0; w < 8; w++) { ts += red[0][w]; tq += red[1][w]; }
    const float mu = ts * (1.f / 1024.f);
    const float var = tq * (1.f / 1024.f) - mu * mu;
    const float rstd = rsqrtf(var + 1e-5f);

    float4 g4 = *(const float4*)(gamma + (tid << 2));
    float4 b4 = *(const float4*)(beta + (tid << 2));
    float2 gt0 = __half22float2(*(const __half2*)(G + base));
    float2 gt1 = __half22float2(*(const __half2*)(G + base + 2));
    float o0 = ((a.x - mu) * rstd * g4.x + b4.x) * gt0.x;
    float o1 = ((a.y - mu) * rstd * g4.y + b4.y) * gt0.y;
    float o2 = ((bb.x - mu) * rstd * g4.z + b4.z) * gt1.x;
    float o3 = ((bb.y - mu) * rstd * g4.w + b4.w) * gt1.y;
    *(__half2*)(OLN + base) = __floats2half2_rn(o0, o1);
    *(__half2*)(OLN + base + 2) = __floats2half2_rn(o2, o3);
}

// ---------------------------------------------------------------------------
extern "C" void kernel_launch(void* const* d_in, const int* in_sizes, int n_in,
                              void* d_out, int out_size)
{
    const float* x     = (const float*)d_in[0];
    const float* Wq    = (const float*)d_in[1];
    const float* Wk    = (const float*)d_in[2];
    const float* Wv    = (const float*)d_in[3];
    const float* Wo    = (const float*)d_in[4];
    const float* gamma = (const float*)d_in[5];
    const float* beta  = (const float*)d_in[6];
    const float* Wg1   = (const float*)d_in[7];
    const float* Wg2   = (const float*)d_in[8];
    float* out = (float*)d_out;

    void *pX, *pWqkv, *pWo, *pWg1, *pWg2, *pQKV, *pG1, *pGATE, *pO, *pOLN, *pM, *pKV;
    cudaGetSymbolAddress(&pX, hX);
    cudaGetSymbolAddress(&pWqkv, hWqkv);
    cudaGetSymbolAddress(&pWo, hWo);
    cudaGetSymbolAddress(&pWg1, hWg1);
    cudaGetSymbolAddress(&pWg2, hWg2);
    cudaGetSymbolAddress(&pQKV, hQKV);
    cudaGetSymbolAddress(&pG1, hG1);
    cudaGetSymbolAddress(&pGATE, hGATE);
    cudaGetSymbolAddress(&pO, hO);
    cudaGetSymbolAddress(&pOLN, hOLN);
    cudaGetSymbolAddress(&pM, gM);
    cudaGetSymbolAddress(&pKV, gKV);
    __half* X = (__half*)pX;       __half* Wqkv = (__half*)pWqkv;
    __half* WoH = (__half*)pWo;    __half* Wg1H = (__half*)pWg1;
    __half* Wg2H = (__half*)pWg2;  __half* QKV = (__half*)pQKV;
    __half* G1 = (__half*)pG1;     __half* GATE = (__half*)pGATE;
    __half* O = (__half*)pO;       __half* OLN = (__half*)pOLN;
    float* Mb = (float*)pM;        float* KVb = (float*)pKV;

    // smem sizes
    const int smG128 = 3 * (128 * 72 + 64 * 136) * 2;   // 107520
    const int smG64  = 3 * (128 * 72 + 64 * 72) * 2;    //  82944
    const int smAttn = 544 + (128 * 72 + 128 * 72 + 64 * 72 + 128 * 136) * 2;
    const int smCkv  = 544 + (128 * 72 + 128 * 72) * 2;
    cudaFuncSetAttribute(tgemm_h<1, 128, true>,
                         cudaFuncAttributeMaxDynamicSharedMemorySize, smG128);
    cudaFuncSetAttribute(tgemm_h<2, 128, true>,
                         cudaFuncAttributeMaxDynamicSharedMemorySize, smG128);
    cudaFuncSetAttribute(tgemm_h<0, 128, false>,
                         cudaFuncAttributeMaxDynamicSharedMemorySize, smG128);
    cudaFuncSetAttribute(tgemm_h<0, 64, true>,
                         cudaFuncAttributeMaxDynamicSharedMemorySize, smG64);
    cudaFuncSetAttribute(attn_h_k,
                         cudaFuncAttributeMaxDynamicSharedMemorySize, smAttn);
    cudaFuncSetAttribute(ckv_h_k,
                         cudaFuncAttributeMaxDynamicSharedMemorySize, smCkv);

    cudaStream_t s0 = 0;            // capture (default) stream
    cudaStream_t s1 = g_s1;

    // ---- fork: s1 joins the capture graph ----
    cudaEventRecord(g_evFork, s0);
    cudaStreamWaitEvent(s1, g_evFork, 0);

    dim3 tB(256);

    // s1: weight converts (independent of x)
    cvt_qkv_k<<<1024, 256, 0, s1>>>(Wq, Wqkv, 0);
    cvt_qkv_k<<<1024, 256, 0, s1>>>(Wk, Wqkv, 1024);
    cvt_qkv_k<<<1024, 256, 0, s1>>>(Wv, Wqkv, 2048);
    cudaEventRecord(g_evW, s1);                     // Wqkv ready
    cvt_half_k<<<EDIM * EDIM / 1024, 256, 0, s1>>>((const float4*)Wo, WoH);
    cvt_half_k<<<EDIM * DH / 1024, 256, 0, s1>>>((const float4*)Wg1, Wg1H);
    cvt_half_k<<<EDIM * DH / 1024, 256, 0, s1>>>((const float4*)Wg2, Wg2H);

    // s0: convert x
    cvt_half_k<<<MDIM * EDIM / 1024, 256, 0, s0>>>((const float4*)x, X);
    cudaEventRecord(g_evX, s0);                     // X ready

    // s1: gate path (needs X)
    cudaStreamWaitEvent(s1, g_evX, 0);
    tgemm_h<0, 64, true><<<dim3(1, MDIM / 128), tB, smG64, s1>>>(
        X, Wg1H, G1, MDIM, DH, EDIM);
    tgemm_h<2, 128, true><<<dim3(EDIM / 128, MDIM / 128), tB, smG128, s1>>>(
        G1, Wg2H, GATE, MDIM, EDIM, DH);
    cudaEventRecord(g_evGate, s1);                  // GATE + WoH ready

    // s0: main chain
    cudaStreamWaitEvent(s0, g_evW, 0);
    tgemm_h<1, 128, true><<<dim3(QKVN / 128, MDIM / 128), tB, smG128, s0>>>(
        X, Wqkv, QKV, MDIM, QKVN, EDIM);
    ckv_h_k<<<dim3(NCH, BHN), tB, smCkv, s0>>>(QKV, Mb);
    kv_scan_k<<<dim3(16, BHN), tB, 0, s0>>>(Mb, KVb);
    attn_h_k<<<dim3(NCH, BHN), tB, smAttn, s0>>>(QKV, KVb, O);

    // join: LN needs GATE (and final GEMM needs WoH)
    cudaStreamWaitEvent(s0, g_evGate, 0);
    ln_gate_h<<<MDIM, tB, 0, s0>>>(O, GATE, gamma, beta, OLN);
    tgemm_h<0, 128, false><<<dim3(EDIM / 128, MDIM / 128), tB, smG128, s0>>>(
        OLN, WoH, out, MDIM, EDIM, EDIM);
}